// round 14
// baseline (speedup 1.0000x reference)
#include <cuda_runtime.h>
#include <cuda_bf16.h>
#include <math.h>
#include <stdint.h>
#include <string.h>

// Problem constants
static constexpr int LEN = 2048;
static constexpr int HH  = 1024;
static constexpr int DIN = 2048;
static constexpr int NS  = 16;
static constexpr int RR  = 64;
static constexpr int KC  = 4;
static constexpr int XDP = 128;     // padded x_dbl width (96 -> 128)
static constexpr int KSPLIT = 8;    // split-K factor for x_proj
static constexpr int NCH_L = 16;    // scan L-chunks
static constexpr int LCH  = LEN / NCH_L;   // 128
static constexpr int NDB  = DIN / 16;      // 128 d-blocks

// fp32 scratch
__device__ __align__(16) float g_xz[(size_t)LEN * 2 * DIN];
__device__ __align__(16) float g_xs[(size_t)LEN * DIN];
__device__ __align__(16) float g_xdbl[(size_t)LEN * XDP];
__device__ __align__(16) float g_delta[(size_t)LEN * DIN];
__device__ __align__(16) float g_xpart[(size_t)KSPLIT * LEN * XDP];
__device__ __align__(16) float g_carryA[(size_t)NCH_L * DIN * NS];
__device__ __align__(16) float g_carryH[(size_t)NCH_L * DIN * NS];
__device__ int g_scanflag[NCH_L * NDB];

// bf16 hi/lo operand buffers in SW128-swizzled 16KB-tile layout
__device__ __align__(1024) __nv_bfloat16 g_x_hi[(size_t)LEN * HH];
__device__ __align__(1024) __nv_bfloat16 g_x_lo[(size_t)LEN * HH];
__device__ __align__(1024) __nv_bfloat16 g_inw_hi[(size_t)2*DIN * HH];
__device__ __align__(1024) __nv_bfloat16 g_inw_lo[(size_t)2*DIN * HH];
__device__ __align__(1024) __nv_bfloat16 g_xs_hi[(size_t)LEN * DIN];
__device__ __align__(1024) __nv_bfloat16 g_xs_lo[(size_t)LEN * DIN];
__device__ __align__(1024) __nv_bfloat16 g_wpad_hi[(size_t)XDP * DIN];
__device__ __align__(1024) __nv_bfloat16 g_wpad_lo[(size_t)XDP * DIN];
__device__ __align__(1024) __nv_bfloat16 g_xdbl_hi[(size_t)LEN * XDP];
__device__ __align__(1024) __nv_bfloat16 g_xdbl_lo[(size_t)LEN * XDP];
__device__ __align__(1024) __nv_bfloat16 g_dtw_hi[(size_t)DIN * RR];
__device__ __align__(1024) __nv_bfloat16 g_dtw_lo[(size_t)DIN * RR];
__device__ __align__(1024) __nv_bfloat16 g_y_hi[(size_t)LEN * DIN];
__device__ __align__(1024) __nv_bfloat16 g_y_lo[(size_t)LEN * DIN];
__device__ __align__(1024) __nv_bfloat16 g_outw_hi[(size_t)HH * DIN];
__device__ __align__(1024) __nv_bfloat16 g_outw_lo[(size_t)HH * DIN];

#if defined(__CUDA_ARCH_FEAT_SM103_ALL) || defined(__CUDA_ARCH_FEAT_SM100_ALL)
#define HAS_TCGEN05 1
#else
#define HAS_TCGEN05 0
#endif

// ---------------------------------------------------------------------------
// helpers
// ---------------------------------------------------------------------------
__device__ __forceinline__ uint32_t smem_to_u32(const void* smem_ptr) {
    uint32_t addr;
    asm("{ .reg .u64 tmp; cvta.to.shared.u64 tmp, %1; cvt.u32.u64 %0, tmp; }"
        : "=r"(addr) : "l"(smem_ptr));
    return addr;
}

#define SMEM_SWIZZLE_128B(byte_offset) \
    ((byte_offset) ^ (((byte_offset) >> 3) & 0x70))

__device__ __forceinline__ uint32_t tiled_off(int row, int col, int K) {
    uint32_t tile = (uint32_t)(row >> 7) * (uint32_t)(K >> 6) + (uint32_t)(col >> 6);
    uint32_t in = (uint32_t)((row & 127) * 128 + (col & 63) * 2);
    return (tile << 14) + SMEM_SWIZZLE_128B(in);
}

static constexpr uint64_t SMEM_DESC_BASE_SW128 =
    (uint64_t(2)  << 61) | (uint64_t(1) << 46) | (uint64_t(64) << 32) | (uint64_t(1) << 16);
#define MAKE_SMEM_DESC(base_addr) \
    (SMEM_DESC_BASE_SW128 | ((uint64_t)((base_addr) >> 4) & 0x3FFF))

#if HAS_TCGEN05

#define TCGEN05_ALLOC(smem_result_addr, nCols) \
    asm volatile("tcgen05.alloc.cta_group::1.sync.aligned.shared::cta.b32 [%0], %1;" \
        :: "r"((uint32_t)(smem_result_addr)), "r"((uint32_t)(nCols)) : "memory")
#define TCGEN05_DEALLOC(tmem_addr, nCols) \
    asm volatile("tcgen05.dealloc.cta_group::1.sync.aligned.b32 %0, %1;" \
        :: "r"(tmem_addr), "r"((uint32_t)(nCols)))
#define TCGEN05_RELINQUISH_ALLOC_PERMIT() \
    asm volatile("tcgen05.relinquish_alloc_permit.cta_group::1.sync.aligned;")
#define TCGEN05_COMMIT(mbar_smem_addr) \
    asm volatile("tcgen05.commit.cta_group::1.mbarrier::arrive::one.shared::cluster.b64 [%0];" \
        :: "r"((uint32_t)(mbar_smem_addr)) : "memory")
#define TCGEN05_WAIT_LD() \
    asm volatile("tcgen05.wait::ld.sync.aligned;" ::: "memory")
#define TCGEN05_FENCE_AFTER() \
    asm volatile("tcgen05.fence::after_thread_sync;" ::: "memory")

#define MBARRIER_INIT(mbar_smem_addr, count) \
    asm volatile("mbarrier.init.shared.b64 [%0], %1;" \
        :: "r"((uint32_t)(mbar_smem_addr)), "r"((uint32_t)(count)) : "memory")

#define MBARRIER_EXPECT_TX(mbar_smem_addr, tx_bytes) \
    asm volatile("mbarrier.arrive.expect_tx.shared.b64 _, [%0], %1;" \
        :: "r"((uint32_t)(mbar_smem_addr)), "r"((uint32_t)(tx_bytes)) : "memory")

#define MBARRIER_WAIT_PARITY(mbar_smem_addr, phase_parity) do { \
    uint32_t _mbar = (uint32_t)(mbar_smem_addr); \
    uint32_t _parity = (uint32_t)(phase_parity); \
    uint32_t _done; \
    asm volatile( \
        "{\n\t.reg .pred p;\n\t" \
        "mbarrier.try_wait.parity.acquire.cta.shared::cta.b64 p, [%1], %2;\n\t" \
        "selp.b32 %0, 1, 0, p;\n\t}" \
        : "=r"(_done) : "r"(_mbar), "r"(_parity) : "memory"); \
    if (!_done) { \
        asm volatile( \
            "{\n\t.reg .pred P1;\n\t" \
            "WAIT_LOOP_%=:\n\t" \
            "mbarrier.try_wait.parity.acquire.cta.shared::cta.b64 P1, [%0], %1, 0x989680;\n\t" \
            "@P1 bra.uni WAIT_DONE_%=;\n\t" \
            "bra.uni WAIT_LOOP_%=;\n\t" \
            "WAIT_DONE_%=:\n\t}" \
            :: "r"(_mbar), "r"(_parity) : "memory"); \
    } \
} while(0)

#define TCGEN05_LD_32X32B_X32(r, tmem_addr) \
    asm volatile( \
        "tcgen05.ld.sync.aligned.32x32b.x32.b32 " \
        "{%0, %1, %2, %3, %4, %5, %6, %7, " \
        " %8, %9, %10, %11, %12, %13, %14, %15, " \
        " %16, %17, %18, %19, %20, %21, %22, %23, " \
        " %24, %25, %26, %27, %28, %29, %30, %31}, [%32];" \
        : "=r"((r)[0]),  "=r"((r)[1]),  "=r"((r)[2]),  "=r"((r)[3]), \
          "=r"((r)[4]),  "=r"((r)[5]),  "=r"((r)[6]),  "=r"((r)[7]), \
          "=r"((r)[8]),  "=r"((r)[9]),  "=r"((r)[10]), "=r"((r)[11]), \
          "=r"((r)[12]), "=r"((r)[13]), "=r"((r)[14]), "=r"((r)[15]), \
          "=r"((r)[16]), "=r"((r)[17]), "=r"((r)[18]), "=r"((r)[19]), \
          "=r"((r)[20]), "=r"((r)[21]), "=r"((r)[22]), "=r"((r)[23]), \
          "=r"((r)[24]), "=r"((r)[25]), "=r"((r)[26]), "=r"((r)[27]), \
          "=r"((r)[28]), "=r"((r)[29]), "=r"((r)[30]), "=r"((r)[31]) \
        : "r"(tmem_addr))

__device__ __forceinline__ void mma_f16_ss(uint32_t d_tmem, uint64_t a_desc,
                                           uint64_t b_desc, uint32_t idesc,
                                           bool accum) {
    uint32_t en = accum ? 1u : 0u;
    asm volatile(
        "{\n\t.reg .pred p;\n\t"
        "setp.ne.u32 p, %5, 0;\n\t"
        "tcgen05.mma.cta_group::1.kind::f16 [%0], %1, %2, %3, {%4, %4, %4, %4}, p;\n\t"
        "}"
        :: "r"(d_tmem), "l"(a_desc), "l"(b_desc), "r"(idesc), "r"(0u), "r"(en)
        : "memory");
}

__device__ __forceinline__ void bulk_cp(uint32_t dst, const void* src,
                                        uint32_t bytes, uint32_t mbar) {
    asm volatile(
        "cp.async.bulk.shared::cta.global.mbarrier::complete_tx::bytes [%0], [%1], %2, [%3];"
        :: "r"(dst), "l"(src), "r"(bytes), "r"(mbar) : "memory");
}

#endif // HAS_TCGEN05

// ---------------------------------------------------------------------------
// tcgen05 GEMM (unchanged from R13): 3-stage bulk-copy pipeline, BM=BN=128.
// ---------------------------------------------------------------------------
static constexpr int TILE_B = 16384;
static constexpr int STAGE_B = 4 * TILE_B;              // 64 KB
static constexpr int BUF0 = 1024;
static constexpr int GEMM_SMEM = BUF0 + 3 * STAGE_B;    // 197632 B

template <int EPI>
__global__ __launch_bounds__(256) void gemm_tc(
    const __nv_bfloat16* __restrict__ a_hi, const __nv_bfloat16* __restrict__ a_lo,
    const __nv_bfloat16* __restrict__ b_hi, const __nv_bfloat16* __restrict__ b_lo,
    const float* __restrict__ bias, float* __restrict__ C,
    int nkA, int nkB, int nch, int ldc)
{
#if HAS_TCGEN05
    extern __shared__ char smem[];
    uint32_t sb = smem_to_u32(smem);
    const int tid = threadIdx.x;
    const int wid = tid >> 5, lane = tid & 31;
    const int bm = blockIdx.y * 128, bn = blockIdx.x * 128;
    const int kc0 = blockIdx.z * nch;
    C += (size_t)blockIdx.z * (size_t)(gridDim.y * 128) * ldc;

    if (wid == 0) TCGEN05_ALLOC(sb, 128);
    if (tid == 0) {
        MBARRIER_INIT(sb + 8, 1);  MBARRIER_INIT(sb + 16, 1); MBARRIER_INIT(sb + 24, 1);
        MBARRIER_INIT(sb + 32, 1); MBARRIER_INIT(sb + 40, 1); MBARRIER_INIT(sb + 48, 1);
    }
    __syncthreads();
    uint32_t tmem;
    asm volatile("ld.shared.b32 %0, [%1];" : "=r"(tmem) : "r"(sb));

    const uint32_t idesc = (1u << 4) | (1u << 7) | (1u << 10) |
                           (16u << 17) | (8u << 24);

    if (tid == 0) {
        const char* pah = (const char*)a_hi;
        const char* pal = (const char*)a_lo;
        const char* pbh = (const char*)b_hi;
        const char* pbl = (const char*)b_lo;
        const size_t abase = (size_t)blockIdx.y * nkA + kc0;
        const size_t bbase = (size_t)blockIdx.x * nkB + kc0;

        auto fill = [&](int f) {
            int slot = f % 3;
            uint32_t st = sb + BUF0 + (uint32_t)slot * STAGE_B;
            uint32_t mb = sb + 8 + 8 * slot;
            MBARRIER_EXPECT_TX(mb, STAGE_B);
            bulk_cp(st,              pah + (abase + f) * TILE_B, TILE_B, mb);
            bulk_cp(st + TILE_B,     pal + (abase + f) * TILE_B, TILE_B, mb);
            bulk_cp(st + 2 * TILE_B, pbh + (bbase + f) * TILE_B, TILE_B, mb);
            bulk_cp(st + 3 * TILE_B, pbl + (bbase + f) * TILE_B, TILE_B, mb);
        };

        int npro = nch < 3 ? nch : 3;
        for (int s = 0; s < npro; s++) fill(s);

        for (int c = 0; c < nch; c++) {
            const int slot = c % 3;
            const int ph = (c / 3) & 1;
            const uint32_t st = sb + BUF0 + (uint32_t)slot * STAGE_B;
            MBARRIER_WAIT_PARITY(sb + 8 + 8 * slot, ph);
            uint64_t ah = MAKE_SMEM_DESC(st);
            uint64_t al = MAKE_SMEM_DESC(st + TILE_B);
            uint64_t bh = MAKE_SMEM_DESC(st + 2 * TILE_B);
            uint64_t bl = MAKE_SMEM_DESC(st + 3 * TILE_B);
            const bool accc = (c > 0);
#pragma unroll
            for (int k = 0; k < 4; k++) {
                mma_f16_ss(tmem, ah + k * 2, bh + k * 2, idesc, accc || k > 0);
                mma_f16_ss(tmem, ah + k * 2, bl + k * 2, idesc, true);
                mma_f16_ss(tmem, al + k * 2, bh + k * 2, idesc, true);
            }
            TCGEN05_COMMIT(sb + 32 + 8 * slot);
            if (c + 3 < nch) {
                MBARRIER_WAIT_PARITY(sb + 32 + 8 * slot, ph);
                fill(c + 3);
            }
        }
        MBARRIER_WAIT_PARITY(sb + 32 + 8 * ((nch - 1) % 3), ((nch - 1) / 3) & 1);
    }

    __syncthreads();
    TCGEN05_FENCE_AFTER();

    if (wid < 4) {
        const int row = bm + wid * 32 + lane;
#pragma unroll
        for (int c32 = 0; c32 < 4; c32++) {
            uint32_t r[32];
            TCGEN05_LD_32X32B_X32(r, tmem + c32 * 32);
            TCGEN05_WAIT_LD();
            float* crow = &C[(size_t)row * ldc + bn + c32 * 32];
#pragma unroll
            for (int j = 0; j < 8; j++) {
                float4 v;
                v.x = __uint_as_float(r[4 * j + 0]);
                v.y = __uint_as_float(r[4 * j + 1]);
                v.z = __uint_as_float(r[4 * j + 2]);
                v.w = __uint_as_float(r[4 * j + 3]);
                if (EPI >= 1) {
                    float4 bv = *reinterpret_cast<const float4*>(
                        &bias[bn + c32 * 32 + 4 * j]);
                    v.x += bv.x; v.y += bv.y; v.z += bv.z; v.w += bv.w;
                }
                if (EPI == 2) {
                    v.x = (v.x > 20.f) ? v.x : log1pf(__expf(v.x));
                    v.y = (v.y > 20.f) ? v.y : log1pf(__expf(v.y));
                    v.z = (v.z > 20.f) ? v.z : log1pf(__expf(v.z));
                    v.w = (v.w > 20.f) ? v.w : log1pf(__expf(v.w));
                }
                *reinterpret_cast<float4*>(&crow[4 * j]) = v;
            }
        }
    }
    __syncthreads();
    if (wid == 0) {
        TCGEN05_RELINQUISH_ALLOC_PERMIT();
        TCGEN05_DEALLOC(tmem, 128);
    }
#endif // HAS_TCGEN05
}

// ---------------------------------------------------------------------------
// Fused fp32 -> tiled-swizzled bf16 hi/lo split for all 5 operand tensors.
// ---------------------------------------------------------------------------
struct SplitSeg {
    const float* src; char* hi; char* lo;
    int K; int rows_valid; int start;
};
struct SplitArgs { SplitSeg s[5]; int total; };

__global__ __launch_bounds__(256) void split_all_kernel(SplitArgs a)
{
    int i = blockIdx.x * 256 + threadIdx.x;
    if (i >= a.total) return;
    int si = 0;
#pragma unroll
    for (int t = 1; t < 5; t++)
        if (i >= a.s[t].start) si = t;
    const SplitSeg g = a.s[si];
    int li = i - g.start;
    int kq = g.K >> 2;
    int row = li / kq, col = (li - row * kq) * 4;
    float4 v = make_float4(0.f, 0.f, 0.f, 0.f);
    if (row < g.rows_valid)
        v = *reinterpret_cast<const float4*>(&g.src[(size_t)row * g.K + col]);
    __nv_bfloat16 h0 = __float2bfloat16(v.x), h1 = __float2bfloat16(v.y);
    __nv_bfloat16 h2 = __float2bfloat16(v.z), h3 = __float2bfloat16(v.w);
    __nv_bfloat16 l0 = __float2bfloat16(v.x - __bfloat162float(h0));
    __nv_bfloat16 l1 = __float2bfloat16(v.y - __bfloat162float(h1));
    __nv_bfloat16 l2 = __float2bfloat16(v.z - __bfloat162float(h2));
    __nv_bfloat16 l3 = __float2bfloat16(v.w - __bfloat162float(h3));
    uint32_t off = tiled_off(row, col, g.K);
    __nv_bfloat162 hA(h0, h1), hB(h2, h3), lA(l0, l1), lB(l2, l3);
    uint2 hu, lu;
    memcpy(&hu.x, &hA, 4); memcpy(&hu.y, &hB, 4);
    memcpy(&lu.x, &lA, 4); memcpy(&lu.y, &lB, 4);
    *reinterpret_cast<uint2*>(g.hi + off) = hu;
    *reinterpret_cast<uint2*>(g.lo + off) = lu;
}

__device__ __forceinline__ void split_store_tiled(float v, __nv_bfloat16* hi,
                                                  __nv_bfloat16* lo,
                                                  int row, int col, int K) {
    uint32_t off = tiled_off(row, col, K);
    __nv_bfloat16 h = __float2bfloat16(v);
    *reinterpret_cast<__nv_bfloat16*>((char*)hi + off) = h;
    *reinterpret_cast<__nv_bfloat16*>((char*)lo + off) =
        __float2bfloat16(v - __bfloat162float(h));
}

// ---------------------------------------------------------------------------
// conv1d (K=4, causal) + SiLU; writes xs fp32 + tiled bf16 hi/lo
// ---------------------------------------------------------------------------
__global__ __launch_bounds__(256) void conv_silu_kernel(
    const float* __restrict__ conv_w, const float* __restrict__ conv_b,
    const float* __restrict__ xz, float* __restrict__ xs,
    __nv_bfloat16* __restrict__ xs_hi, __nv_bfloat16* __restrict__ xs_lo)
{
    int idx = blockIdx.x * blockDim.x + threadIdx.x;
    if (idx >= LEN * DIN) return;
    int l = idx / DIN, d = idx % DIN;
    float acc = conv_b[d];
#pragma unroll
    for (int k = 0; k < KC; k++) {
        int ls = l - (KC - 1) + k;
        if (ls >= 0)
            acc += conv_w[d * KC + k] * xz[(size_t)ls * (2 * DIN) + d];
    }
    float v = acc / (1.f + __expf(-acc));
    xs[idx] = v;
    split_store_tiled(v, xs_hi, xs_lo, l, d, DIN);
}

// ---------------------------------------------------------------------------
// reduce split-K partials -> xdbl fp32 + tiled hi/lo
// ---------------------------------------------------------------------------
__global__ __launch_bounds__(256) void reduce_xdbl_kernel(
    const float* __restrict__ part, float* __restrict__ xdbl,
    __nv_bfloat16* __restrict__ hi, __nv_bfloat16* __restrict__ lo)
{
    int i = blockIdx.x * 256 + threadIdx.x;
    if (i >= LEN * XDP) return;
    float s = 0.f;
#pragma unroll
    for (int z = 0; z < KSPLIT; z++)
        s += part[(size_t)z * LEN * XDP + i];
    xdbl[i] = s;
    split_store_tiled(s, hi, lo, i / XDP, i % XDP, XDP);
}

// ---------------------------------------------------------------------------
// FUSED chunked selective scan with decoupled lookback.
// grid (NDB, NCH_L) — chunk index is the SLOW dim so predecessor chunks have
// lower linear block IDs (forward-progress for the lookback spin).
// Pass A: local carry from staged smem; publish carry + release flag.
// Lookback: combine predecessors' carries (spin on their flags).
// Pass B: full scan from smem with fused +xs*D and *silu(res) epilogue.
// ---------------------------------------------------------------------------
static constexpr int SCAN_CH = 16;

__global__ __launch_bounds__(256) void scan_fused_kernel(
    const float* __restrict__ A_log, const float* __restrict__ Dp,
    const float* __restrict__ xdbl, const float* __restrict__ delta_g,
    const float* __restrict__ xs_g, const float* __restrict__ xz,
    float* __restrict__ carryA, float* __restrict__ carryH,
    int* __restrict__ flags,
    __nv_bfloat16* __restrict__ y_hi, __nv_bfloat16* __restrict__ y_lo)
{
    __shared__ float sBC[LCH][32];        // B | C        16 KB
    __shared__ float sDelta[LCH][SCAN_CH];//               8 KB
    __shared__ float sXs[LCH][SCAN_CH];   //               8 KB
    __shared__ float sRes[LCH][SCAN_CH];  // silu(res)     8 KB
    __shared__ float sY[LCH][SCAN_CH];    //               8 KB

    const int d0 = blockIdx.x * SCAN_CH;
    const int jch = blockIdx.y;
    const int lbase = jch * LCH;
    const int tid = threadIdx.x;
    const int warp = tid >> 5, lane = tid & 31;
    const int sub = lane >> 4, n = lane & 15;
    const int ch = warp * 2 + sub;
    const int d = d0 + ch;

    const float a = -__expf(A_log[d * NS + n]);
    const float Dv = Dp[d];

    // stage entire chunk into smem (single global read)
    for (int i = tid; i < LCH * 32; i += 256) {
        int row = i >> 5, c = i & 31;
        sBC[row][c] = xdbl[(size_t)(lbase + row) * XDP + RR + c];
    }
    for (int i = tid; i < LCH * SCAN_CH; i += 256) {
        int row = i >> 4, c = i & 15;
        sDelta[row][c] = delta_g[(size_t)(lbase + row) * DIN + d0 + c];
        sXs[row][c]    = xs_g[(size_t)(lbase + row) * DIN + d0 + c];
        float r = xz[(size_t)(lbase + row) * (2 * DIN) + DIN + d0 + c];
        sRes[row][c]   = r / (1.f + __expf(-r));
    }
    __syncthreads();

    // Pass A: local carry (h from 0, product of dA)
    {
        float h = 0.f, ap = 1.f;
#pragma unroll 4
        for (int l = 0; l < LCH; l++) {
            float dv = sDelta[l][ch];
            float dA = __expf(dv * a);
            h = dA * h + (dv * sXs[l][ch]) * sBC[l][n];
            ap *= dA;
        }
        size_t o = (size_t)jch * DIN * NS + (size_t)d * NS + n;
        carryA[o] = ap;
        carryH[o] = h;
    }
    __threadfence();
    __syncthreads();
    if (tid == 0)
        atomicExch(&flags[jch * NDB + blockIdx.x], 1);

    // Lookback: combine carries of chunks 0..jch-1 (forward order)
    float h = 0.f;
    for (int j = 0; j < jch; j++) {
        if (tid == 0) {
            while (atomicAdd(&flags[j * NDB + blockIdx.x], 0) == 0) { }
        }
        __syncthreads();
        __threadfence();
        size_t o = (size_t)j * DIN * NS + (size_t)d * NS + n;
        float ca = *(volatile const float*)&carryA[o];
        float chh = *(volatile const float*)&carryH[o];
        h = ca * h + chh;
    }

    // Pass B: full scan with carry-in, emit y
#pragma unroll 4
    for (int l = 0; l < LCH; l++) {
        float dv = sDelta[l][ch];
        float xv = sXs[l][ch];
        float dA = __expf(dv * a);
        h = dA * h + (dv * xv) * sBC[l][n];
        float p = sBC[l][16 + n] * h;
        p += __shfl_xor_sync(0xffffffffu, p, 8);
        p += __shfl_xor_sync(0xffffffffu, p, 4);
        p += __shfl_xor_sync(0xffffffffu, p, 2);
        p += __shfl_xor_sync(0xffffffffu, p, 1);
        if (n == 0)
            sY[l][ch] = (p + xv * Dv) * sRes[l][ch];
    }
    __syncthreads();

    for (int i = tid; i < LCH * SCAN_CH; i += 256) {
        int row = i >> 4, c = i & 15;
        split_store_tiled(sY[row][c], y_hi, y_lo, lbase + row, d0 + c, DIN);
    }
}

// ---------------------------------------------------------------------------

extern "C" void kernel_launch(void* const* d_in, const int* in_sizes, int n_in,
                              void* d_out, int out_size)
{
    const float* x       = (const float*)d_in[0];
    const float* in_w    = (const float*)d_in[1];
    const float* in_b    = (const float*)d_in[2];
    const float* conv_w  = (const float*)d_in[3];
    const float* conv_b  = (const float*)d_in[4];
    const float* xproj_w = (const float*)d_in[5];
    const float* dt_w    = (const float*)d_in[6];
    const float* dt_b    = (const float*)d_in[7];
    const float* A_log   = (const float*)d_in[8];
    const float* Dp      = (const float*)d_in[9];
    const float* out_w   = (const float*)d_in[10];
    float* out = (float*)d_out;

    #define SYM(T, name) T* name; { void* p_; cudaGetSymbolAddress(&p_, g_##name); name = (T*)p_; }
    SYM(float, xz) SYM(float, xs) SYM(float, xdbl) SYM(float, delta) SYM(float, xpart)
    SYM(float, carryA) SYM(float, carryH)
    SYM(int, scanflag)
    SYM(__nv_bfloat16, x_hi)    SYM(__nv_bfloat16, x_lo)
    SYM(__nv_bfloat16, inw_hi)  SYM(__nv_bfloat16, inw_lo)
    SYM(__nv_bfloat16, xs_hi)   SYM(__nv_bfloat16, xs_lo)
    SYM(__nv_bfloat16, wpad_hi) SYM(__nv_bfloat16, wpad_lo)
    SYM(__nv_bfloat16, xdbl_hi) SYM(__nv_bfloat16, xdbl_lo)
    SYM(__nv_bfloat16, dtw_hi)  SYM(__nv_bfloat16, dtw_lo)
    SYM(__nv_bfloat16, y_hi)    SYM(__nv_bfloat16, y_lo)
    SYM(__nv_bfloat16, outw_hi) SYM(__nv_bfloat16, outw_lo)
    #undef SYM

    static bool attr_done = false;
    if (!attr_done) {
        cudaFuncSetAttribute((const void*)gemm_tc<0>, cudaFuncAttributeMaxDynamicSharedMemorySize, GEMM_SMEM);
        cudaFuncSetAttribute((const void*)gemm_tc<1>, cudaFuncAttributeMaxDynamicSharedMemorySize, GEMM_SMEM);
        cudaFuncSetAttribute((const void*)gemm_tc<2>, cudaFuncAttributeMaxDynamicSharedMemorySize, GEMM_SMEM);
        attr_done = true;
    }

    // reset lookback flags (graph-capturable async memset)
    cudaMemsetAsync(scanflag, 0, sizeof(int) * NCH_L * NDB);

    // 0) fused operand formatting (tiled + swizzled bf16 hi/lo), one launch
    {
        SplitArgs a;
        int n_x    = LEN * HH / 4;
        int n_inw  = 2 * DIN * HH / 4;
        int n_outw = HH * DIN / 4;
        int n_dtw  = DIN * RR / 4;
        int n_wpad = XDP * DIN / 4;
        a.s[0] = { x,       (char*)x_hi,    (char*)x_lo,    HH,  LEN,        0 };
        a.s[1] = { in_w,    (char*)inw_hi,  (char*)inw_lo,  HH,  2 * DIN,    n_x };
        a.s[2] = { out_w,   (char*)outw_hi, (char*)outw_lo, DIN, HH,         n_x + n_inw };
        a.s[3] = { dt_w,    (char*)dtw_hi,  (char*)dtw_lo,  RR,  DIN,        n_x + n_inw + n_outw };
        a.s[4] = { xproj_w, (char*)wpad_hi, (char*)wpad_lo, DIN, RR + 2*NS,  n_x + n_inw + n_outw + n_dtw };
        a.total = n_x + n_inw + n_outw + n_dtw + n_wpad;
        split_all_kernel<<<(a.total + 255) / 256, 256>>>(a);
    }

    // 1) in_proj: xz[2048,4096] = x @ in_w^T + b
    {
        dim3 grid(2 * DIN / 128, LEN / 128, 1);
        gemm_tc<1><<<grid, 256, GEMM_SMEM>>>(x_hi, x_lo, inw_hi, inw_lo, in_b, xz,
                                             HH / 64, HH / 64, HH / 64, 2 * DIN);
    }
    // 2) conv + silu -> xs fp32 + tiled hi/lo
    conv_silu_kernel<<<(LEN * DIN) / 256, 256>>>(conv_w, conv_b, xz, xs, xs_hi, xs_lo);
    // 3) x_proj split-K: xpart[8][2048][128] = xs @ wpad^T
    {
        dim3 grid(1, LEN / 128, KSPLIT);
        gemm_tc<0><<<grid, 256, GEMM_SMEM>>>(xs_hi, xs_lo, wpad_hi, wpad_lo, nullptr,
                                             xpart, DIN / 64, DIN / 64,
                                             DIN / 64 / KSPLIT, XDP);
    }
    // 3b) reduce -> xdbl fp32 + tiled hi/lo
    reduce_xdbl_kernel<<<(LEN * XDP + 255) / 256, 256>>>(xpart, xdbl, xdbl_hi, xdbl_lo);
    // 4) dt_proj + softplus: delta[2048,2048]  (K=64, single chunk)
    {
        dim3 grid(DIN / 128, LEN / 128, 1);
        gemm_tc<2><<<grid, 256, GEMM_SMEM>>>(xdbl_hi, xdbl_lo, dtw_hi, dtw_lo, dt_b,
                                             delta, XDP / 64, RR / 64, 1, DIN);
    }
    // 5) fused chunked scan (decoupled lookback)
    {
        dim3 g(NDB, NCH_L);
        scan_fused_kernel<<<g, 256>>>(A_log, Dp, xdbl, delta, xs, xz,
                                      carryA, carryH, scanflag, y_hi, y_lo);
    }
    // 6) out_proj: out[2048,1024] = y @ out_w^T
    {
        dim3 grid(HH / 128, LEN / 128, 1);
        gemm_tc<0><<<grid, 256, GEMM_SMEM>>>(y_hi, y_lo, outw_hi, outw_lo, nullptr,
                                             out, DIN / 64, DIN / 64, DIN / 64, HH);
    }
}

// round 15
// speedup vs baseline: 1.1048x; 1.1048x over previous
#include <cuda_runtime.h>
#include <cuda_bf16.h>
#include <math.h>
#include <stdint.h>
#include <string.h>

// Problem constants
static constexpr int LEN = 2048;
static constexpr int HH  = 1024;
static constexpr int DIN = 2048;
static constexpr int NS  = 16;
static constexpr int RR  = 64;
static constexpr int KC  = 4;
static constexpr int XDP = 128;     // padded x_dbl width (96 -> 128)
static constexpr int KSPLIT = 8;    // split-K factor for x_proj
static constexpr int NCH_L = 16;    // scan L-chunks
static constexpr int LCH  = LEN / NCH_L;   // 128

// fp32 scratch
__device__ __align__(16) float g_xz[(size_t)LEN * 2 * DIN];
__device__ __align__(16) float g_xs[(size_t)LEN * DIN];
__device__ __align__(16) float g_xdbl[(size_t)LEN * XDP];
__device__ __align__(16) float g_delta[(size_t)LEN * DIN];
__device__ __align__(16) float g_xpart[(size_t)KSPLIT * LEN * XDP];
__device__ __align__(16) float g_carryA[(size_t)NCH_L * DIN * NS];
__device__ __align__(16) float g_carryH[(size_t)NCH_L * DIN * NS];

// bf16 operand buffers: interleaved hi/lo in SW128-swizzled 32KB-tile-pair
// layout. tensor [rows, K] -> tile pair (rowpanel=row/128, kchunk=col/64);
// byte off = pair*32768 + part*16384 + SW128((row%128)*128 + (col%64)*2)
__device__ __align__(1024) __nv_bfloat16 g_x_t[(size_t)2 * LEN * HH];
__device__ __align__(1024) __nv_bfloat16 g_inw_t[(size_t)2 * 2*DIN * HH];
__device__ __align__(1024) __nv_bfloat16 g_xs_t[(size_t)2 * LEN * DIN];
__device__ __align__(1024) __nv_bfloat16 g_wpad_t[(size_t)2 * XDP * DIN];
__device__ __align__(1024) __nv_bfloat16 g_xdbl_t[(size_t)2 * LEN * XDP];
__device__ __align__(1024) __nv_bfloat16 g_dtw_t[(size_t)2 * DIN * RR];
__device__ __align__(1024) __nv_bfloat16 g_y_t[(size_t)2 * LEN * DIN];
__device__ __align__(1024) __nv_bfloat16 g_outw_t[(size_t)2 * HH * DIN];

#if defined(__CUDA_ARCH_FEAT_SM103_ALL) || defined(__CUDA_ARCH_FEAT_SM100_ALL)
#define HAS_TCGEN05 1
#else
#define HAS_TCGEN05 0
#endif

// ---------------------------------------------------------------------------
// helpers
// ---------------------------------------------------------------------------
__device__ __forceinline__ uint32_t smem_to_u32(const void* smem_ptr) {
    uint32_t addr;
    asm("{ .reg .u64 tmp; cvta.to.shared.u64 tmp, %1; cvt.u32.u64 %0, tmp; }"
        : "=r"(addr) : "l"(smem_ptr));
    return addr;
}

#define SMEM_SWIZZLE_128B(byte_offset) \
    ((byte_offset) ^ (((byte_offset) >> 3) & 0x70))

// interleaved tiled-swizzled byte offset: part 0=hi, 1=lo
__device__ __forceinline__ uint32_t tiled_off2(int row, int col, int K, int part) {
    uint32_t pair = (uint32_t)(row >> 7) * (uint32_t)(K >> 6) + (uint32_t)(col >> 6);
    uint32_t in = (uint32_t)((row & 127) * 128 + (col & 63) * 2);
    return (pair << 15) + ((uint32_t)part << 14) + SMEM_SWIZZLE_128B(in);
}

static constexpr uint64_t SMEM_DESC_BASE_SW128 =
    (uint64_t(2)  << 61) | (uint64_t(1) << 46) | (uint64_t(64) << 32) | (uint64_t(1) << 16);
#define MAKE_SMEM_DESC(base_addr) \
    (SMEM_DESC_BASE_SW128 | ((uint64_t)((base_addr) >> 4) & 0x3FFF))

#if HAS_TCGEN05

#define TCGEN05_ALLOC(smem_result_addr, nCols) \
    asm volatile("tcgen05.alloc.cta_group::1.sync.aligned.shared::cta.b32 [%0], %1;" \
        :: "r"((uint32_t)(smem_result_addr)), "r"((uint32_t)(nCols)) : "memory")
#define TCGEN05_DEALLOC(tmem_addr, nCols) \
    asm volatile("tcgen05.dealloc.cta_group::1.sync.aligned.b32 %0, %1;" \
        :: "r"(tmem_addr), "r"((uint32_t)(nCols)))
#define TCGEN05_RELINQUISH_ALLOC_PERMIT() \
    asm volatile("tcgen05.relinquish_alloc_permit.cta_group::1.sync.aligned;")
#define TCGEN05_COMMIT(mbar_smem_addr) \
    asm volatile("tcgen05.commit.cta_group::1.mbarrier::arrive::one.shared::cluster.b64 [%0];" \
        :: "r"((uint32_t)(mbar_smem_addr)) : "memory")
#define TCGEN05_WAIT_LD() \
    asm volatile("tcgen05.wait::ld.sync.aligned;" ::: "memory")
#define TCGEN05_FENCE_AFTER() \
    asm volatile("tcgen05.fence::after_thread_sync;" ::: "memory")

#define MBARRIER_INIT(mbar_smem_addr, count) \
    asm volatile("mbarrier.init.shared.b64 [%0], %1;" \
        :: "r"((uint32_t)(mbar_smem_addr)), "r"((uint32_t)(count)) : "memory")

#define MBARRIER_EXPECT_TX(mbar_smem_addr, tx_bytes) \
    asm volatile("mbarrier.arrive.expect_tx.shared.b64 _, [%0], %1;" \
        :: "r"((uint32_t)(mbar_smem_addr)), "r"((uint32_t)(tx_bytes)) : "memory")

#define MBARRIER_WAIT_PARITY(mbar_smem_addr, phase_parity) do { \
    uint32_t _mbar = (uint32_t)(mbar_smem_addr); \
    uint32_t _parity = (uint32_t)(phase_parity); \
    uint32_t _done; \
    asm volatile( \
        "{\n\t.reg .pred p;\n\t" \
        "mbarrier.try_wait.parity.acquire.cta.shared::cta.b64 p, [%1], %2;\n\t" \
        "selp.b32 %0, 1, 0, p;\n\t}" \
        : "=r"(_done) : "r"(_mbar), "r"(_parity) : "memory"); \
    if (!_done) { \
        asm volatile( \
            "{\n\t.reg .pred P1;\n\t" \
            "WAIT_LOOP_%=:\n\t" \
            "mbarrier.try_wait.parity.acquire.cta.shared::cta.b64 P1, [%0], %1, 0x989680;\n\t" \
            "@P1 bra.uni WAIT_DONE_%=;\n\t" \
            "bra.uni WAIT_LOOP_%=;\n\t" \
            "WAIT_DONE_%=:\n\t}" \
            :: "r"(_mbar), "r"(_parity) : "memory"); \
    } \
} while(0)

#define TCGEN05_LD_32X32B_X32(r, tmem_addr) \
    asm volatile( \
        "tcgen05.ld.sync.aligned.32x32b.x32.b32 " \
        "{%0, %1, %2, %3, %4, %5, %6, %7, " \
        " %8, %9, %10, %11, %12, %13, %14, %15, " \
        " %16, %17, %18, %19, %20, %21, %22, %23, " \
        " %24, %25, %26, %27, %28, %29, %30, %31}, [%32];" \
        : "=r"((r)[0]),  "=r"((r)[1]),  "=r"((r)[2]),  "=r"((r)[3]), \
          "=r"((r)[4]),  "=r"((r)[5]),  "=r"((r)[6]),  "=r"((r)[7]), \
          "=r"((r)[8]),  "=r"((r)[9]),  "=r"((r)[10]), "=r"((r)[11]), \
          "=r"((r)[12]), "=r"((r)[13]), "=r"((r)[14]), "=r"((r)[15]), \
          "=r"((r)[16]), "=r"((r)[17]), "=r"((r)[18]), "=r"((r)[19]), \
          "=r"((r)[20]), "=r"((r)[21]), "=r"((r)[22]), "=r"((r)[23]), \
          "=r"((r)[24]), "=r"((r)[25]), "=r"((r)[26]), "=r"((r)[27]), \
          "=r"((r)[28]), "=r"((r)[29]), "=r"((r)[30]), "=r"((r)[31]) \
        : "r"(tmem_addr))

__device__ __forceinline__ void mma_f16_ss(uint32_t d_tmem, uint64_t a_desc,
                                           uint64_t b_desc, uint32_t idesc,
                                           bool accum) {
    uint32_t en = accum ? 1u : 0u;
    asm volatile(
        "{\n\t.reg .pred p;\n\t"
        "setp.ne.u32 p, %5, 0;\n\t"
        "tcgen05.mma.cta_group::1.kind::f16 [%0], %1, %2, %3, {%4, %4, %4, %4}, p;\n\t"
        "}"
        :: "r"(d_tmem), "l"(a_desc), "l"(b_desc), "r"(idesc), "r"(0u), "r"(en)
        : "memory");
}

__device__ __forceinline__ void bulk_cp(uint32_t dst, const void* src,
                                        uint32_t bytes, uint32_t mbar) {
    asm volatile(
        "cp.async.bulk.shared::cta.global.mbarrier::complete_tx::bytes [%0], [%1], %2, [%3];"
        :: "r"(dst), "l"(src), "r"(bytes), "r"(mbar) : "memory");
}

#endif // HAS_TCGEN05

// ---------------------------------------------------------------------------
// tcgen05 GEMM: operands in interleaved tiled-swizzled bf16 hi/lo layout;
// each chunk fetched with TWO 32KB cp.async.bulk (A pair, B pair).
// BM=BN=128, BK=64; 3-stage pipeline (prefill 3, fill c+3 after MMA(c)).
// 3-term split (ah*bh + ah*bl + al*bh).
// EPI: 0=none, 1=+bias, 2=softplus(acc+bias).  Split-K via blockIdx.z.
// ---------------------------------------------------------------------------
static constexpr int TILE_B = 16384;
static constexpr int PAIR_B = 32768;
static constexpr int STAGE_B = 4 * TILE_B;              // 64 KB
static constexpr int BUF0 = 1024;
static constexpr int GEMM_SMEM = BUF0 + 3 * STAGE_B;    // 197632 B

template <int EPI>
__global__ __launch_bounds__(256) void gemm_tc(
    const __nv_bfloat16* __restrict__ a_t, const __nv_bfloat16* __restrict__ b_t,
    const float* __restrict__ bias, float* __restrict__ C,
    int nkA, int nkB, int nch, int ldc)
{
#if HAS_TCGEN05
    extern __shared__ char smem[];
    uint32_t sb = smem_to_u32(smem);
    const int tid = threadIdx.x;
    const int wid = tid >> 5, lane = tid & 31;
    const int bm = blockIdx.y * 128, bn = blockIdx.x * 128;
    const int kc0 = blockIdx.z * nch;
    C += (size_t)blockIdx.z * (size_t)(gridDim.y * 128) * ldc;

    if (wid == 0) TCGEN05_ALLOC(sb, 128);
    if (tid == 0) {
        MBARRIER_INIT(sb + 8, 1);  MBARRIER_INIT(sb + 16, 1); MBARRIER_INIT(sb + 24, 1);
        MBARRIER_INIT(sb + 32, 1); MBARRIER_INIT(sb + 40, 1); MBARRIER_INIT(sb + 48, 1);
    }
    __syncthreads();
    uint32_t tmem;
    asm volatile("ld.shared.b32 %0, [%1];" : "=r"(tmem) : "r"(sb));

    const uint32_t idesc = (1u << 4) | (1u << 7) | (1u << 10) |
                           (16u << 17) | (8u << 24);

    if (tid == 0) {
        const char* pa = (const char*)a_t;
        const char* pb = (const char*)b_t;
        const size_t abase = (size_t)blockIdx.y * nkA + kc0;
        const size_t bbase = (size_t)blockIdx.x * nkB + kc0;

        auto fill = [&](int f) {
            int slot = f % 3;
            uint32_t st = sb + BUF0 + (uint32_t)slot * STAGE_B;
            uint32_t mb = sb + 8 + 8 * slot;
            MBARRIER_EXPECT_TX(mb, STAGE_B);
            bulk_cp(st,          pa + (abase + f) * PAIR_B, PAIR_B, mb);
            bulk_cp(st + PAIR_B, pb + (bbase + f) * PAIR_B, PAIR_B, mb);
        };

        int npro = nch < 3 ? nch : 3;
        for (int s = 0; s < npro; s++) fill(s);

        for (int c = 0; c < nch; c++) {
            const int slot = c % 3;
            const int ph = (c / 3) & 1;
            const uint32_t st = sb + BUF0 + (uint32_t)slot * STAGE_B;
            MBARRIER_WAIT_PARITY(sb + 8 + 8 * slot, ph);   // fill(c) landed
            uint64_t ah = MAKE_SMEM_DESC(st);
            uint64_t al = MAKE_SMEM_DESC(st + TILE_B);
            uint64_t bh = MAKE_SMEM_DESC(st + 2 * TILE_B);
            uint64_t bl = MAKE_SMEM_DESC(st + 3 * TILE_B);
            const bool accc = (c > 0);
#pragma unroll
            for (int k = 0; k < 4; k++) {
                mma_f16_ss(tmem, ah + k * 2, bh + k * 2, idesc, accc || k > 0);
                mma_f16_ss(tmem, ah + k * 2, bl + k * 2, idesc, true);
                mma_f16_ss(tmem, al + k * 2, bh + k * 2, idesc, true);
            }
            TCGEN05_COMMIT(sb + 32 + 8 * slot);
            if (c + 3 < nch) {
                MBARRIER_WAIT_PARITY(sb + 32 + 8 * slot, ph);  // MMA(c) done
                fill(c + 3);
            }
        }
        MBARRIER_WAIT_PARITY(sb + 32 + 8 * ((nch - 1) % 3), ((nch - 1) / 3) & 1);
    }

    __syncthreads();
    TCGEN05_FENCE_AFTER();

    if (wid < 4) {
        const int row = bm + wid * 32 + lane;
#pragma unroll
        for (int c32 = 0; c32 < 4; c32++) {
            uint32_t r[32];
            TCGEN05_LD_32X32B_X32(r, tmem + c32 * 32);
            TCGEN05_WAIT_LD();
            float* crow = &C[(size_t)row * ldc + bn + c32 * 32];
#pragma unroll
            for (int j = 0; j < 8; j++) {
                float4 v;
                v.x = __uint_as_float(r[4 * j + 0]);
                v.y = __uint_as_float(r[4 * j + 1]);
                v.z = __uint_as_float(r[4 * j + 2]);
                v.w = __uint_as_float(r[4 * j + 3]);
                if (EPI >= 1) {
                    float4 bv = *reinterpret_cast<const float4*>(
                        &bias[bn + c32 * 32 + 4 * j]);
                    v.x += bv.x; v.y += bv.y; v.z += bv.z; v.w += bv.w;
                }
                if (EPI == 2) {
                    v.x = (v.x > 20.f) ? v.x : log1pf(__expf(v.x));
                    v.y = (v.y > 20.f) ? v.y : log1pf(__expf(v.y));
                    v.z = (v.z > 20.f) ? v.z : log1pf(__expf(v.z));
                    v.w = (v.w > 20.f) ? v.w : log1pf(__expf(v.w));
                }
                *reinterpret_cast<float4*>(&crow[4 * j]) = v;
            }
        }
    }
    __syncthreads();
    if (wid == 0) {
        TCGEN05_RELINQUISH_ALLOC_PERMIT();
        TCGEN05_DEALLOC(tmem, 128);
    }
#endif // HAS_TCGEN05
}

// ---------------------------------------------------------------------------
// Fused fp32 -> interleaved tiled-swizzled bf16 hi/lo split (5 tensors).
// ---------------------------------------------------------------------------
struct SplitSeg {
    const float* src; char* dst;
    int K; int rows_valid; int start;
};
struct SplitArgs { SplitSeg s[5]; int total; };

__global__ __launch_bounds__(256) void split_all_kernel(SplitArgs a)
{
    int i = blockIdx.x * 256 + threadIdx.x;
    if (i >= a.total) return;
    int si = 0;
#pragma unroll
    for (int t = 1; t < 5; t++)
        if (i >= a.s[t].start) si = t;
    const SplitSeg g = a.s[si];
    int li = i - g.start;
    int kq = g.K >> 2;
    int row = li / kq, col = (li - row * kq) * 4;
    float4 v = make_float4(0.f, 0.f, 0.f, 0.f);
    if (row < g.rows_valid)
        v = *reinterpret_cast<const float4*>(&g.src[(size_t)row * g.K + col]);
    __nv_bfloat16 h0 = __float2bfloat16(v.x), h1 = __float2bfloat16(v.y);
    __nv_bfloat16 h2 = __float2bfloat16(v.z), h3 = __float2bfloat16(v.w);
    __nv_bfloat16 l0 = __float2bfloat16(v.x - __bfloat162float(h0));
    __nv_bfloat16 l1 = __float2bfloat16(v.y - __bfloat162float(h1));
    __nv_bfloat16 l2 = __float2bfloat16(v.z - __bfloat162float(h2));
    __nv_bfloat16 l3 = __float2bfloat16(v.w - __bfloat162float(h3));
    uint32_t offh = tiled_off2(row, col, g.K, 0);
    uint32_t offl = tiled_off2(row, col, g.K, 1);
    __nv_bfloat162 hA(h0, h1), hB(h2, h3), lA(l0, l1), lB(l2, l3);
    uint2 hu, lu;
    memcpy(&hu.x, &hA, 4); memcpy(&hu.y, &hB, 4);
    memcpy(&lu.x, &lA, 4); memcpy(&lu.y, &lB, 4);
    *reinterpret_cast<uint2*>(g.dst + offh) = hu;
    *reinterpret_cast<uint2*>(g.dst + offl) = lu;
}

__device__ __forceinline__ void split_store_tiled2(float v, __nv_bfloat16* dst,
                                                   int row, int col, int K) {
    __nv_bfloat16 h = __float2bfloat16(v);
    *reinterpret_cast<__nv_bfloat16*>((char*)dst + tiled_off2(row, col, K, 0)) = h;
    *reinterpret_cast<__nv_bfloat16*>((char*)dst + tiled_off2(row, col, K, 1)) =
        __float2bfloat16(v - __bfloat162float(h));
}

// ---------------------------------------------------------------------------
// conv1d (K=4, causal) + SiLU; writes xs fp32 + interleaved tiled bf16
// ---------------------------------------------------------------------------
__global__ __launch_bounds__(256) void conv_silu_kernel(
    const float* __restrict__ conv_w, const float* __restrict__ conv_b,
    const float* __restrict__ xz, float* __restrict__ xs,
    __nv_bfloat16* __restrict__ xs_t)
{
    int idx = blockIdx.x * blockDim.x + threadIdx.x;
    if (idx >= LEN * DIN) return;
    int l = idx / DIN, d = idx % DIN;
    float acc = conv_b[d];
#pragma unroll
    for (int k = 0; k < KC; k++) {
        int ls = l - (KC - 1) + k;
        if (ls >= 0)
            acc += conv_w[d * KC + k] * xz[(size_t)ls * (2 * DIN) + d];
    }
    float v = acc / (1.f + __expf(-acc));
    xs[idx] = v;
    split_store_tiled2(v, xs_t, l, d, DIN);
}

// ---------------------------------------------------------------------------
// reduce split-K partials -> xdbl fp32 + interleaved tiled bf16
// ---------------------------------------------------------------------------
__global__ __launch_bounds__(256) void reduce_xdbl_kernel(
    const float* __restrict__ part, float* __restrict__ xdbl,
    __nv_bfloat16* __restrict__ xdbl_t)
{
    int i = blockIdx.x * 256 + threadIdx.x;
    if (i >= LEN * XDP) return;
    float s = 0.f;
#pragma unroll
    for (int z = 0; z < KSPLIT; z++)
        s += part[(size_t)z * LEN * XDP + i];
    xdbl[i] = s;
    split_store_tiled2(s, xdbl_t, i / XDP, i % XDP, XDP);
}

// ---------------------------------------------------------------------------
// Chunked selective scan (two-phase, R13 structure).
// ---------------------------------------------------------------------------
static constexpr int SCAN_TL = 64;
static constexpr int SCAN_CH = 16;

__global__ __launch_bounds__(256) void scan_p1_kernel(
    const float* __restrict__ A_log,
    const float* __restrict__ xdbl, const float* __restrict__ delta_g,
    const float* __restrict__ xs_g,
    float* __restrict__ carryA, float* __restrict__ carryH)
{
    __shared__ float sB[SCAN_TL][NS];
    __shared__ float sDelta[SCAN_TL][SCAN_CH];
    __shared__ float sXs[SCAN_TL][SCAN_CH];

    const int d0 = blockIdx.x * SCAN_CH;
    const int jch = blockIdx.y;
    const int lbase = jch * LCH;
    const int tid = threadIdx.x;
    const int warp = tid >> 5, lane = tid & 31;
    const int sub = lane >> 4, n = lane & 15;
    const int ch = warp * 2 + sub;
    const int d = d0 + ch;

    const float a = -__expf(A_log[d * NS + n]);
    float h = 0.f, ap = 1.f;

    for (int l0 = lbase; l0 < lbase + LCH; l0 += SCAN_TL) {
        for (int i = tid; i < SCAN_TL * NS; i += 256) {
            int row = i >> 4, c = i & 15;
            sB[row][c] = xdbl[(size_t)(l0 + row) * XDP + RR + c];
        }
        for (int i = tid; i < SCAN_TL * SCAN_CH; i += 256) {
            int row = i >> 4, c = i & 15;
            sDelta[row][c] = delta_g[(size_t)(l0 + row) * DIN + d0 + c];
            sXs[row][c]    = xs_g[(size_t)(l0 + row) * DIN + d0 + c];
        }
        __syncthreads();
#pragma unroll 4
        for (int l = 0; l < SCAN_TL; l++) {
            float dv = sDelta[l][ch];
            float dA = __expf(dv * a);
            h = dA * h + (dv * sXs[l][ch]) * sB[l][n];
            ap *= dA;
        }
        __syncthreads();
    }
    size_t o = (size_t)jch * DIN * NS + (size_t)d * NS + n;
    carryA[o] = ap;
    carryH[o] = h;
}

__global__ __launch_bounds__(256) void scan_p3_kernel(
    const float* __restrict__ A_log, const float* __restrict__ Dp,
    const float* __restrict__ xdbl, const float* __restrict__ delta_g,
    const float* __restrict__ xs_g, const float* __restrict__ xz,
    const float* __restrict__ carryA, const float* __restrict__ carryH,
    __nv_bfloat16* __restrict__ y_t)
{
    __shared__ float sBC[SCAN_TL][32];
    __shared__ float sDelta[SCAN_TL][SCAN_CH];
    __shared__ float sXs[SCAN_TL][SCAN_CH];
    __shared__ float sRes[SCAN_TL][SCAN_CH];
    __shared__ float sY[SCAN_TL][SCAN_CH];

    const int d0 = blockIdx.x * SCAN_CH;
    const int jch = blockIdx.y;
    const int lbase = jch * LCH;
    const int tid = threadIdx.x;
    const int warp = tid >> 5, lane = tid & 31;
    const int sub = lane >> 4, n = lane & 15;
    const int ch = warp * 2 + sub;
    const int d = d0 + ch;

    const float a = -__expf(A_log[d * NS + n]);
    const float Dv = Dp[d];

    float h = 0.f;
    for (int j = 0; j < jch; j++) {
        size_t o = (size_t)j * DIN * NS + (size_t)d * NS + n;
        h = carryA[o] * h + carryH[o];
    }

    for (int l0 = lbase; l0 < lbase + LCH; l0 += SCAN_TL) {
        for (int i = tid; i < SCAN_TL * 32; i += 256) {
            int row = i >> 5, c = i & 31;
            sBC[row][c] = xdbl[(size_t)(l0 + row) * XDP + RR + c];
        }
        for (int i = tid; i < SCAN_TL * SCAN_CH; i += 256) {
            int row = i >> 4, c = i & 15;
            sDelta[row][c] = delta_g[(size_t)(l0 + row) * DIN + d0 + c];
            sXs[row][c]    = xs_g[(size_t)(l0 + row) * DIN + d0 + c];
            float r = xz[(size_t)(l0 + row) * (2 * DIN) + DIN + d0 + c];
            sRes[row][c]   = r / (1.f + __expf(-r));
        }
        __syncthreads();

#pragma unroll 4
        for (int l = 0; l < SCAN_TL; l++) {
            float dv = sDelta[l][ch];
            float xv = sXs[l][ch];
            float dA = __expf(dv * a);
            h = dA * h + (dv * xv) * sBC[l][n];
            float p = sBC[l][16 + n] * h;
            p += __shfl_xor_sync(0xffffffffu, p, 8);
            p += __shfl_xor_sync(0xffffffffu, p, 4);
            p += __shfl_xor_sync(0xffffffffu, p, 2);
            p += __shfl_xor_sync(0xffffffffu, p, 1);
            if (n == 0)
                sY[l][ch] = (p + xv * Dv) * sRes[l][ch];
        }
        __syncthreads();

        for (int i = tid; i < SCAN_TL * SCAN_CH; i += 256) {
            int row = i >> 4, c = i & 15;
            split_store_tiled2(sY[row][c], y_t, l0 + row, d0 + c, DIN);
        }
        __syncthreads();
    }
}

// ---------------------------------------------------------------------------

extern "C" void kernel_launch(void* const* d_in, const int* in_sizes, int n_in,
                              void* d_out, int out_size)
{
    const float* x       = (const float*)d_in[0];
    const float* in_w    = (const float*)d_in[1];
    const float* in_b    = (const float*)d_in[2];
    const float* conv_w  = (const float*)d_in[3];
    const float* conv_b  = (const float*)d_in[4];
    const float* xproj_w = (const float*)d_in[5];
    const float* dt_w    = (const float*)d_in[6];
    const float* dt_b    = (const float*)d_in[7];
    const float* A_log   = (const float*)d_in[8];
    const float* Dp      = (const float*)d_in[9];
    const float* out_w   = (const float*)d_in[10];
    float* out = (float*)d_out;

    #define SYM(T, name) T* name; { void* p_; cudaGetSymbolAddress(&p_, g_##name); name = (T*)p_; }
    SYM(float, xz) SYM(float, xs) SYM(float, xdbl) SYM(float, delta) SYM(float, xpart)
    SYM(float, carryA) SYM(float, carryH)
    SYM(__nv_bfloat16, x_t)    SYM(__nv_bfloat16, inw_t)
    SYM(__nv_bfloat16, xs_t)   SYM(__nv_bfloat16, wpad_t)
    SYM(__nv_bfloat16, xdbl_t) SYM(__nv_bfloat16, dtw_t)
    SYM(__nv_bfloat16, y_t)    SYM(__nv_bfloat16, outw_t)
    #undef SYM

    static bool attr_done = false;
    if (!attr_done) {
        cudaFuncSetAttribute((const void*)gemm_tc<0>, cudaFuncAttributeMaxDynamicSharedMemorySize, GEMM_SMEM);
        cudaFuncSetAttribute((const void*)gemm_tc<1>, cudaFuncAttributeMaxDynamicSharedMemorySize, GEMM_SMEM);
        cudaFuncSetAttribute((const void*)gemm_tc<2>, cudaFuncAttributeMaxDynamicSharedMemorySize, GEMM_SMEM);
        attr_done = true;
    }

    // 0) fused operand formatting (interleaved tiled bf16 hi/lo), one launch
    {
        SplitArgs a;
        int n_x    = LEN * HH / 4;
        int n_inw  = 2 * DIN * HH / 4;
        int n_outw = HH * DIN / 4;
        int n_dtw  = DIN * RR / 4;
        int n_wpad = XDP * DIN / 4;
        a.s[0] = { x,       (char*)x_t,    HH,  LEN,        0 };
        a.s[1] = { in_w,    (char*)inw_t,  HH,  2 * DIN,    n_x };
        a.s[2] = { out_w,   (char*)outw_t, DIN, HH,         n_x + n_inw };
        a.s[3] = { dt_w,    (char*)dtw_t,  RR,  DIN,        n_x + n_inw + n_outw };
        a.s[4] = { xproj_w, (char*)wpad_t, DIN, RR + 2*NS,  n_x + n_inw + n_outw + n_dtw };
        a.total = n_x + n_inw + n_outw + n_dtw + n_wpad;
        split_all_kernel<<<(a.total + 255) / 256, 256>>>(a);
    }

    // 1) in_proj: xz[2048,4096] = x @ in_w^T + b
    {
        dim3 grid(2 * DIN / 128, LEN / 128, 1);
        gemm_tc<1><<<grid, 256, GEMM_SMEM>>>(x_t, inw_t, in_b, xz,
                                             HH / 64, HH / 64, HH / 64, 2 * DIN);
    }
    // 2) conv + silu -> xs fp32 + interleaved tiled bf16
    conv_silu_kernel<<<(LEN * DIN) / 256, 256>>>(conv_w, conv_b, xz, xs, xs_t);
    // 3) x_proj split-K: xpart[8][2048][128] = xs @ wpad^T
    {
        dim3 grid(1, LEN / 128, KSPLIT);
        gemm_tc<0><<<grid, 256, GEMM_SMEM>>>(xs_t, wpad_t, nullptr,
                                             xpart, DIN / 64, DIN / 64,
                                             DIN / 64 / KSPLIT, XDP);
    }
    // 3b) reduce -> xdbl fp32 + interleaved tiled bf16
    reduce_xdbl_kernel<<<(LEN * XDP + 255) / 256, 256>>>(xpart, xdbl, xdbl_t);
    // 4) dt_proj + softplus: delta[2048,2048]  (K=64, single chunk)
    {
        dim3 grid(DIN / 128, LEN / 128, 1);
        gemm_tc<2><<<grid, 256, GEMM_SMEM>>>(xdbl_t, dtw_t, dt_b,
                                             delta, XDP / 64, RR / 64, 1, DIN);
    }
    // 5) chunked scan: phase 1 (carries), phase 3 (prefix + y + epilogue)
    {
        dim3 g1(DIN / SCAN_CH, NCH_L);
        scan_p1_kernel<<<g1, 256>>>(A_log, xdbl, delta, xs, carryA, carryH);
        scan_p3_kernel<<<g1, 256>>>(A_log, Dp, xdbl, delta, xs, xz,
                                    carryA, carryH, y_t);
    }
    // 6) out_proj: out[2048,1024] = y @ out_w^T
    {
        dim3 grid(HH / 128, LEN / 128, 1);
        gemm_tc<0><<<grid, 256, GEMM_SMEM>>>(y_t, outw_t, nullptr,
                                             out, DIN / 64, DIN / 64, DIN / 64, HH);
    }
}

// round 16
// speedup vs baseline: 1.1390x; 1.0309x over previous
#include <cuda_runtime.h>
#include <cuda_bf16.h>
#include <math.h>
#include <stdint.h>
#include <string.h>

// Problem constants
static constexpr int LEN = 2048;
static constexpr int HH  = 1024;
static constexpr int DIN = 2048;
static constexpr int NS  = 16;
static constexpr int RR  = 64;
static constexpr int KC  = 4;
static constexpr int XDP = 128;     // padded x_dbl width (96 -> 128)
static constexpr int KSPLIT = 8;    // split-K factor for x_proj
static constexpr int NCH_L = 16;    // scan L-chunks
static constexpr int LCH  = LEN / NCH_L;   // 128

// fp32 scratch
__device__ __align__(16) float g_xz[(size_t)LEN * 2 * DIN];
__device__ __align__(16) float g_xs[(size_t)LEN * DIN];
__device__ __align__(16) float g_xdbl[(size_t)LEN * XDP];
__device__ __align__(16) float g_delta[(size_t)LEN * DIN];
__device__ __align__(16) float g_xpart[(size_t)KSPLIT * LEN * XDP];
__device__ __align__(16) float g_carryA[(size_t)NCH_L * DIN * NS];
__device__ __align__(16) float g_carryH[(size_t)NCH_L * DIN * NS];

// bf16 operand buffers: interleaved hi/lo in SW128-swizzled 32KB-tile-pair
// layout. tensor [rows, K] -> tile pair (rowpanel=row/128, kchunk=col/64);
// byte off = pair*32768 + part*16384 + SW128((row%128)*128 + (col%64)*2)
__device__ __align__(1024) __nv_bfloat16 g_x_t[(size_t)2 * LEN * HH];
__device__ __align__(1024) __nv_bfloat16 g_inw_t[(size_t)2 * 2*DIN * HH];
__device__ __align__(1024) __nv_bfloat16 g_xs_t[(size_t)2 * LEN * DIN];
__device__ __align__(1024) __nv_bfloat16 g_wpad_t[(size_t)2 * XDP * DIN];
__device__ __align__(1024) __nv_bfloat16 g_xdbl_t[(size_t)2 * LEN * XDP];
__device__ __align__(1024) __nv_bfloat16 g_dtw_t[(size_t)2 * DIN * RR];
__device__ __align__(1024) __nv_bfloat16 g_y_t[(size_t)2 * LEN * DIN];
__device__ __align__(1024) __nv_bfloat16 g_outw_t[(size_t)2 * HH * DIN];

#if defined(__CUDA_ARCH_FEAT_SM103_ALL) || defined(__CUDA_ARCH_FEAT_SM100_ALL)
#define HAS_TCGEN05 1
#else
#define HAS_TCGEN05 0
#endif

// ---------------------------------------------------------------------------
// helpers
// ---------------------------------------------------------------------------
__device__ __forceinline__ uint32_t smem_to_u32(const void* smem_ptr) {
    uint32_t addr;
    asm("{ .reg .u64 tmp; cvta.to.shared.u64 tmp, %1; cvt.u32.u64 %0, tmp; }"
        : "=r"(addr) : "l"(smem_ptr));
    return addr;
}

#define SMEM_SWIZZLE_128B(byte_offset) \
    ((byte_offset) ^ (((byte_offset) >> 3) & 0x70))

// interleaved tiled-swizzled byte offset: part 0=hi, 1=lo
__device__ __forceinline__ uint32_t tiled_off2(int row, int col, int K, int part) {
    uint32_t pair = (uint32_t)(row >> 7) * (uint32_t)(K >> 6) + (uint32_t)(col >> 6);
    uint32_t in = (uint32_t)((row & 127) * 128 + (col & 63) * 2);
    return (pair << 15) + ((uint32_t)part << 14) + SMEM_SWIZZLE_128B(in);
}

static constexpr uint64_t SMEM_DESC_BASE_SW128 =
    (uint64_t(2)  << 61) | (uint64_t(1) << 46) | (uint64_t(64) << 32) | (uint64_t(1) << 16);
#define MAKE_SMEM_DESC(base_addr) \
    (SMEM_DESC_BASE_SW128 | ((uint64_t)((base_addr) >> 4) & 0x3FFF))

#if HAS_TCGEN05

#define TCGEN05_ALLOC(smem_result_addr, nCols) \
    asm volatile("tcgen05.alloc.cta_group::1.sync.aligned.shared::cta.b32 [%0], %1;" \
        :: "r"((uint32_t)(smem_result_addr)), "r"((uint32_t)(nCols)) : "memory")
#define TCGEN05_DEALLOC(tmem_addr, nCols) \
    asm volatile("tcgen05.dealloc.cta_group::1.sync.aligned.b32 %0, %1;" \
        :: "r"(tmem_addr), "r"((uint32_t)(nCols)))
#define TCGEN05_RELINQUISH_ALLOC_PERMIT() \
    asm volatile("tcgen05.relinquish_alloc_permit.cta_group::1.sync.aligned;")
#define TCGEN05_COMMIT(mbar_smem_addr) \
    asm volatile("tcgen05.commit.cta_group::1.mbarrier::arrive::one.shared::cluster.b64 [%0];" \
        :: "r"((uint32_t)(mbar_smem_addr)) : "memory")
#define TCGEN05_WAIT_LD() \
    asm volatile("tcgen05.wait::ld.sync.aligned;" ::: "memory")
#define TCGEN05_FENCE_AFTER() \
    asm volatile("tcgen05.fence::after_thread_sync;" ::: "memory")

#define MBARRIER_INIT(mbar_smem_addr, count) \
    asm volatile("mbarrier.init.shared.b64 [%0], %1;" \
        :: "r"((uint32_t)(mbar_smem_addr)), "r"((uint32_t)(count)) : "memory")

#define MBARRIER_EXPECT_TX(mbar_smem_addr, tx_bytes) \
    asm volatile("mbarrier.arrive.expect_tx.shared.b64 _, [%0], %1;" \
        :: "r"((uint32_t)(mbar_smem_addr)), "r"((uint32_t)(tx_bytes)) : "memory")

#define MBARRIER_WAIT_PARITY(mbar_smem_addr, phase_parity) do { \
    uint32_t _mbar = (uint32_t)(mbar_smem_addr); \
    uint32_t _parity = (uint32_t)(phase_parity); \
    uint32_t _done; \
    asm volatile( \
        "{\n\t.reg .pred p;\n\t" \
        "mbarrier.try_wait.parity.acquire.cta.shared::cta.b64 p, [%1], %2;\n\t" \
        "selp.b32 %0, 1, 0, p;\n\t}" \
        : "=r"(_done) : "r"(_mbar), "r"(_parity) : "memory"); \
    if (!_done) { \
        asm volatile( \
            "{\n\t.reg .pred P1;\n\t" \
            "WAIT_LOOP_%=:\n\t" \
            "mbarrier.try_wait.parity.acquire.cta.shared::cta.b64 P1, [%0], %1, 0x989680;\n\t" \
            "@P1 bra.uni WAIT_DONE_%=;\n\t" \
            "bra.uni WAIT_LOOP_%=;\n\t" \
            "WAIT_DONE_%=:\n\t}" \
            :: "r"(_mbar), "r"(_parity) : "memory"); \
    } \
} while(0)

#define TCGEN05_LD_32X32B_X32(r, tmem_addr) \
    asm volatile( \
        "tcgen05.ld.sync.aligned.32x32b.x32.b32 " \
        "{%0, %1, %2, %3, %4, %5, %6, %7, " \
        " %8, %9, %10, %11, %12, %13, %14, %15, " \
        " %16, %17, %18, %19, %20, %21, %22, %23, " \
        " %24, %25, %26, %27, %28, %29, %30, %31}, [%32];" \
        : "=r"((r)[0]),  "=r"((r)[1]),  "=r"((r)[2]),  "=r"((r)[3]), \
          "=r"((r)[4]),  "=r"((r)[5]),  "=r"((r)[6]),  "=r"((r)[7]), \
          "=r"((r)[8]),  "=r"((r)[9]),  "=r"((r)[10]), "=r"((r)[11]), \
          "=r"((r)[12]), "=r"((r)[13]), "=r"((r)[14]), "=r"((r)[15]), \
          "=r"((r)[16]), "=r"((r)[17]), "=r"((r)[18]), "=r"((r)[19]), \
          "=r"((r)[20]), "=r"((r)[21]), "=r"((r)[22]), "=r"((r)[23]), \
          "=r"((r)[24]), "=r"((r)[25]), "=r"((r)[26]), "=r"((r)[27]), \
          "=r"((r)[28]), "=r"((r)[29]), "=r"((r)[30]), "=r"((r)[31]) \
        : "r"(tmem_addr))

__device__ __forceinline__ void mma_f16_ss(uint32_t d_tmem, uint64_t a_desc,
                                           uint64_t b_desc, uint32_t idesc,
                                           bool accum) {
    uint32_t en = accum ? 1u : 0u;
    asm volatile(
        "{\n\t.reg .pred p;\n\t"
        "setp.ne.u32 p, %5, 0;\n\t"
        "tcgen05.mma.cta_group::1.kind::f16 [%0], %1, %2, %3, {%4, %4, %4, %4}, p;\n\t"
        "}"
        :: "r"(d_tmem), "l"(a_desc), "l"(b_desc), "r"(idesc), "r"(0u), "r"(en)
        : "memory");
}

__device__ __forceinline__ void bulk_cp(uint32_t dst, const void* src,
                                        uint32_t bytes, uint32_t mbar) {
    asm volatile(
        "cp.async.bulk.shared::cta.global.mbarrier::complete_tx::bytes [%0], [%1], %2, [%3];"
        :: "r"(dst), "l"(src), "r"(bytes), "r"(mbar) : "memory");
}

#endif // HAS_TCGEN05

// ---------------------------------------------------------------------------
// tcgen05 GEMM: operands in interleaved tiled-swizzled bf16 hi/lo layout;
// each chunk fetched with TWO 32KB cp.async.bulk (A pair, B pair).
// BM=BN=128, BK=64; 3-stage pipeline (prefill 3, fill c+3 after MMA(c)).
// 3-term split (ah*bh + ah*bl + al*bh).
// EPI: 0=none, 1=+bias, 2=softplus(acc+bias).  Split-K via blockIdx.z.
// ---------------------------------------------------------------------------
static constexpr int TILE_B = 16384;
static constexpr int PAIR_B = 32768;
static constexpr int STAGE_B = 4 * TILE_B;              // 64 KB
static constexpr int BUF0 = 1024;
static constexpr int GEMM_SMEM = BUF0 + 3 * STAGE_B;    // 197632 B

template <int EPI>
__global__ __launch_bounds__(256) void gemm_tc(
    const __nv_bfloat16* __restrict__ a_t, const __nv_bfloat16* __restrict__ b_t,
    const float* __restrict__ bias, float* __restrict__ C,
    int nkA, int nkB, int nch, int ldc)
{
#if HAS_TCGEN05
    extern __shared__ char smem[];
    uint32_t sb = smem_to_u32(smem);
    const int tid = threadIdx.x;
    const int wid = tid >> 5, lane = tid & 31;
    const int bm = blockIdx.y * 128, bn = blockIdx.x * 128;
    const int kc0 = blockIdx.z * nch;
    C += (size_t)blockIdx.z * (size_t)(gridDim.y * 128) * ldc;

    if (wid == 0) TCGEN05_ALLOC(sb, 128);
    if (tid == 0) {
        MBARRIER_INIT(sb + 8, 1);  MBARRIER_INIT(sb + 16, 1); MBARRIER_INIT(sb + 24, 1);
        MBARRIER_INIT(sb + 32, 1); MBARRIER_INIT(sb + 40, 1); MBARRIER_INIT(sb + 48, 1);
    }
    __syncthreads();
    uint32_t tmem;
    asm volatile("ld.shared.b32 %0, [%1];" : "=r"(tmem) : "r"(sb));

    const uint32_t idesc = (1u << 4) | (1u << 7) | (1u << 10) |
                           (16u << 17) | (8u << 24);

    if (tid == 0) {
        const char* pa = (const char*)a_t;
        const char* pb = (const char*)b_t;
        const size_t abase = (size_t)blockIdx.y * nkA + kc0;
        const size_t bbase = (size_t)blockIdx.x * nkB + kc0;

        auto fill = [&](int f) {
            int slot = f % 3;
            uint32_t st = sb + BUF0 + (uint32_t)slot * STAGE_B;
            uint32_t mb = sb + 8 + 8 * slot;
            MBARRIER_EXPECT_TX(mb, STAGE_B);
            bulk_cp(st,          pa + (abase + f) * PAIR_B, PAIR_B, mb);
            bulk_cp(st + PAIR_B, pb + (bbase + f) * PAIR_B, PAIR_B, mb);
        };

        int npro = nch < 3 ? nch : 3;
        for (int s = 0; s < npro; s++) fill(s);

        for (int c = 0; c < nch; c++) {
            const int slot = c % 3;
            const int ph = (c / 3) & 1;
            const uint32_t st = sb + BUF0 + (uint32_t)slot * STAGE_B;
            MBARRIER_WAIT_PARITY(sb + 8 + 8 * slot, ph);   // fill(c) landed
            uint64_t ah = MAKE_SMEM_DESC(st);
            uint64_t al = MAKE_SMEM_DESC(st + TILE_B);
            uint64_t bh = MAKE_SMEM_DESC(st + 2 * TILE_B);
            uint64_t bl = MAKE_SMEM_DESC(st + 3 * TILE_B);
            const bool accc = (c > 0);
#pragma unroll
            for (int k = 0; k < 4; k++) {
                mma_f16_ss(tmem, ah + k * 2, bh + k * 2, idesc, accc || k > 0);
                mma_f16_ss(tmem, ah + k * 2, bl + k * 2, idesc, true);
                mma_f16_ss(tmem, al + k * 2, bh + k * 2, idesc, true);
            }
            TCGEN05_COMMIT(sb + 32 + 8 * slot);
            if (c + 3 < nch) {
                MBARRIER_WAIT_PARITY(sb + 32 + 8 * slot, ph);  // MMA(c) done
                fill(c + 3);
            }
        }
        MBARRIER_WAIT_PARITY(sb + 32 + 8 * ((nch - 1) % 3), ((nch - 1) / 3) & 1);
    }

    __syncthreads();
    TCGEN05_FENCE_AFTER();

    if (wid < 4) {
        const int row = bm + wid * 32 + lane;
#pragma unroll
        for (int c32 = 0; c32 < 4; c32++) {
            uint32_t r[32];
            TCGEN05_LD_32X32B_X32(r, tmem + c32 * 32);
            TCGEN05_WAIT_LD();
            float* crow = &C[(size_t)row * ldc + bn + c32 * 32];
#pragma unroll
            for (int j = 0; j < 8; j++) {
                float4 v;
                v.x = __uint_as_float(r[4 * j + 0]);
                v.y = __uint_as_float(r[4 * j + 1]);
                v.z = __uint_as_float(r[4 * j + 2]);
                v.w = __uint_as_float(r[4 * j + 3]);
                if (EPI >= 1) {
                    float4 bv = *reinterpret_cast<const float4*>(
                        &bias[bn + c32 * 32 + 4 * j]);
                    v.x += bv.x; v.y += bv.y; v.z += bv.z; v.w += bv.w;
                }
                if (EPI == 2) {
                    v.x = (v.x > 20.f) ? v.x : log1pf(__expf(v.x));
                    v.y = (v.y > 20.f) ? v.y : log1pf(__expf(v.y));
                    v.z = (v.z > 20.f) ? v.z : log1pf(__expf(v.z));
                    v.w = (v.w > 20.f) ? v.w : log1pf(__expf(v.w));
                }
                *reinterpret_cast<float4*>(&crow[4 * j]) = v;
            }
        }
    }
    __syncthreads();
    if (wid == 0) {
        TCGEN05_RELINQUISH_ALLOC_PERMIT();
        TCGEN05_DEALLOC(tmem, 128);
    }
#endif // HAS_TCGEN05
}

// ---------------------------------------------------------------------------
// Fused fp32 -> interleaved tiled-swizzled bf16 hi/lo split (up to 5 tensors).
// ---------------------------------------------------------------------------
struct SplitSeg {
    const float* src; char* dst;
    int K; int rows_valid; int start;
};
struct SplitArgs { SplitSeg s[5]; int total; };

__global__ __launch_bounds__(256) void split_all_kernel(SplitArgs a)
{
    int i = blockIdx.x * 256 + threadIdx.x;
    if (i >= a.total) return;
    int si = 0;
#pragma unroll
    for (int t = 1; t < 5; t++)
        if (i >= a.s[t].start) si = t;
    const SplitSeg g = a.s[si];
    int li = i - g.start;
    int kq = g.K >> 2;
    int row = li / kq, col = (li - row * kq) * 4;
    float4 v = make_float4(0.f, 0.f, 0.f, 0.f);
    if (row < g.rows_valid)
        v = *reinterpret_cast<const float4*>(&g.src[(size_t)row * g.K + col]);
    __nv_bfloat16 h0 = __float2bfloat16(v.x), h1 = __float2bfloat16(v.y);
    __nv_bfloat16 h2 = __float2bfloat16(v.z), h3 = __float2bfloat16(v.w);
    __nv_bfloat16 l0 = __float2bfloat16(v.x - __bfloat162float(h0));
    __nv_bfloat16 l1 = __float2bfloat16(v.y - __bfloat162float(h1));
    __nv_bfloat16 l2 = __float2bfloat16(v.z - __bfloat162float(h2));
    __nv_bfloat16 l3 = __float2bfloat16(v.w - __bfloat162float(h3));
    uint32_t offh = tiled_off2(row, col, g.K, 0);
    uint32_t offl = tiled_off2(row, col, g.K, 1);
    __nv_bfloat162 hA(h0, h1), hB(h2, h3), lA(l0, l1), lB(l2, l3);
    uint2 hu, lu;
    memcpy(&hu.x, &hA, 4); memcpy(&hu.y, &hB, 4);
    memcpy(&lu.x, &lA, 4); memcpy(&lu.y, &lB, 4);
    *reinterpret_cast<uint2*>(g.dst + offh) = hu;
    *reinterpret_cast<uint2*>(g.dst + offl) = lu;
}

__device__ __forceinline__ void split_store_tiled2(float v, __nv_bfloat16* dst,
                                                   int row, int col, int K) {
    __nv_bfloat16 h = __float2bfloat16(v);
    *reinterpret_cast<__nv_bfloat16*>((char*)dst + tiled_off2(row, col, K, 0)) = h;
    *reinterpret_cast<__nv_bfloat16*>((char*)dst + tiled_off2(row, col, K, 1)) =
        __float2bfloat16(v - __bfloat162float(h));
}

// ---------------------------------------------------------------------------
// conv1d (K=4, causal) + SiLU; writes xs fp32 + interleaved tiled bf16
// ---------------------------------------------------------------------------
__global__ __launch_bounds__(256) void conv_silu_kernel(
    const float* __restrict__ conv_w, const float* __restrict__ conv_b,
    const float* __restrict__ xz, float* __restrict__ xs,
    __nv_bfloat16* __restrict__ xs_t)
{
    int idx = blockIdx.x * blockDim.x + threadIdx.x;
    if (idx >= LEN * DIN) return;
    int l = idx / DIN, d = idx % DIN;
    float acc = conv_b[d];
#pragma unroll
    for (int k = 0; k < KC; k++) {
        int ls = l - (KC - 1) + k;
        if (ls >= 0)
            acc += conv_w[d * KC + k] * xz[(size_t)ls * (2 * DIN) + d];
    }
    float v = acc / (1.f + __expf(-acc));
    xs[idx] = v;
    split_store_tiled2(v, xs_t, l, d, DIN);
}

// ---------------------------------------------------------------------------
// reduce split-K partials -> xdbl fp32 + interleaved tiled bf16
// ---------------------------------------------------------------------------
__global__ __launch_bounds__(256) void reduce_xdbl_kernel(
    const float* __restrict__ part, float* __restrict__ xdbl,
    __nv_bfloat16* __restrict__ xdbl_t)
{
    int i = blockIdx.x * 256 + threadIdx.x;
    if (i >= LEN * XDP) return;
    float s = 0.f;
#pragma unroll
    for (int z = 0; z < KSPLIT; z++)
        s += part[(size_t)z * LEN * XDP + i];
    xdbl[i] = s;
    split_store_tiled2(s, xdbl_t, i / XDP, i % XDP, XDP);
}

// ---------------------------------------------------------------------------
// Chunked selective scan (two-phase).
// ---------------------------------------------------------------------------
static constexpr int SCAN_TL = 64;
static constexpr int SCAN_CH = 16;

__global__ __launch_bounds__(256) void scan_p1_kernel(
    const float* __restrict__ A_log,
    const float* __restrict__ xdbl, const float* __restrict__ delta_g,
    const float* __restrict__ xs_g,
    float* __restrict__ carryA, float* __restrict__ carryH)
{
    __shared__ float sB[SCAN_TL][NS];
    __shared__ float sDelta[SCAN_TL][SCAN_CH];
    __shared__ float sXs[SCAN_TL][SCAN_CH];

    const int d0 = blockIdx.x * SCAN_CH;
    const int jch = blockIdx.y;
    const int lbase = jch * LCH;
    const int tid = threadIdx.x;
    const int warp = tid >> 5, lane = tid & 31;
    const int sub = lane >> 4, n = lane & 15;
    const int ch = warp * 2 + sub;
    const int d = d0 + ch;

    const float a = -__expf(A_log[d * NS + n]);
    float h = 0.f, ap = 1.f;

    for (int l0 = lbase; l0 < lbase + LCH; l0 += SCAN_TL) {
        for (int i = tid; i < SCAN_TL * NS; i += 256) {
            int row = i >> 4, c = i & 15;
            sB[row][c] = xdbl[(size_t)(l0 + row) * XDP + RR + c];
        }
        for (int i = tid; i < SCAN_TL * SCAN_CH; i += 256) {
            int row = i >> 4, c = i & 15;
            sDelta[row][c] = delta_g[(size_t)(l0 + row) * DIN + d0 + c];
            sXs[row][c]    = xs_g[(size_t)(l0 + row) * DIN + d0 + c];
        }
        __syncthreads();
#pragma unroll 4
        for (int l = 0; l < SCAN_TL; l++) {
            float dv = sDelta[l][ch];
            float dA = __expf(dv * a);
            h = dA * h + (dv * sXs[l][ch]) * sB[l][n];
            ap *= dA;
        }
        __syncthreads();
    }
    size_t o = (size_t)jch * DIN * NS + (size_t)d * NS + n;
    carryA[o] = ap;
    carryH[o] = h;
}

__global__ __launch_bounds__(256) void scan_p3_kernel(
    const float* __restrict__ A_log, const float* __restrict__ Dp,
    const float* __restrict__ xdbl, const float* __restrict__ delta_g,
    const float* __restrict__ xs_g, const float* __restrict__ xz,
    const float* __restrict__ carryA, const float* __restrict__ carryH,
    __nv_bfloat16* __restrict__ y_t)
{
    __shared__ float sBC[SCAN_TL][32];
    __shared__ float sDelta[SCAN_TL][SCAN_CH];
    __shared__ float sXs[SCAN_TL][SCAN_CH];
    __shared__ float sRes[SCAN_TL][SCAN_CH];
    __shared__ float sY[SCAN_TL][SCAN_CH];

    const int d0 = blockIdx.x * SCAN_CH;
    const int jch = blockIdx.y;
    const int lbase = jch * LCH;
    const int tid = threadIdx.x;
    const int warp = tid >> 5, lane = tid & 31;
    const int sub = lane >> 4, n = lane & 15;
    const int ch = warp * 2 + sub;
    const int d = d0 + ch;

    const float a = -__expf(A_log[d * NS + n]);
    const float Dv = Dp[d];

    float h = 0.f;
    for (int j = 0; j < jch; j++) {
        size_t o = (size_t)j * DIN * NS + (size_t)d * NS + n;
        h = carryA[o] * h + carryH[o];
    }

    for (int l0 = lbase; l0 < lbase + LCH; l0 += SCAN_TL) {
        for (int i = tid; i < SCAN_TL * 32; i += 256) {
            int row = i >> 5, c = i & 31;
            sBC[row][c] = xdbl[(size_t)(l0 + row) * XDP + RR + c];
        }
        for (int i = tid; i < SCAN_TL * SCAN_CH; i += 256) {
            int row = i >> 4, c = i & 15;
            sDelta[row][c] = delta_g[(size_t)(l0 + row) * DIN + d0 + c];
            sXs[row][c]    = xs_g[(size_t)(l0 + row) * DIN + d0 + c];
            float r = xz[(size_t)(l0 + row) * (2 * DIN) + DIN + d0 + c];
            sRes[row][c]   = r / (1.f + __expf(-r));
        }
        __syncthreads();

#pragma unroll 4
        for (int l = 0; l < SCAN_TL; l++) {
            float dv = sDelta[l][ch];
            float xv = sXs[l][ch];
            float dA = __expf(dv * a);
            h = dA * h + (dv * xv) * sBC[l][n];
            float p = sBC[l][16 + n] * h;
            p += __shfl_xor_sync(0xffffffffu, p, 8);
            p += __shfl_xor_sync(0xffffffffu, p, 4);
            p += __shfl_xor_sync(0xffffffffu, p, 2);
            p += __shfl_xor_sync(0xffffffffu, p, 1);
            if (n == 0)
                sY[l][ch] = (p + xv * Dv) * sRes[l][ch];
        }
        __syncthreads();

        for (int i = tid; i < SCAN_TL * SCAN_CH; i += 256) {
            int row = i >> 4, c = i & 15;
            split_store_tiled2(sY[row][c], y_t, l0 + row, d0 + c, DIN);
        }
        __syncthreads();
    }
}

// ---------------------------------------------------------------------------

extern "C" void kernel_launch(void* const* d_in, const int* in_sizes, int n_in,
                              void* d_out, int out_size)
{
    const float* x       = (const float*)d_in[0];
    const float* in_w    = (const float*)d_in[1];
    const float* in_b    = (const float*)d_in[2];
    const float* conv_w  = (const float*)d_in[3];
    const float* conv_b  = (const float*)d_in[4];
    const float* xproj_w = (const float*)d_in[5];
    const float* dt_w    = (const float*)d_in[6];
    const float* dt_b    = (const float*)d_in[7];
    const float* A_log   = (const float*)d_in[8];
    const float* Dp      = (const float*)d_in[9];
    const float* out_w   = (const float*)d_in[10];
    float* out = (float*)d_out;

    #define SYM(T, name) T* name; { void* p_; cudaGetSymbolAddress(&p_, g_##name); name = (T*)p_; }
    SYM(float, xz) SYM(float, xs) SYM(float, xdbl) SYM(float, delta) SYM(float, xpart)
    SYM(float, carryA) SYM(float, carryH)
    SYM(__nv_bfloat16, x_t)    SYM(__nv_bfloat16, inw_t)
    SYM(__nv_bfloat16, xs_t)   SYM(__nv_bfloat16, wpad_t)
    SYM(__nv_bfloat16, xdbl_t) SYM(__nv_bfloat16, dtw_t)
    SYM(__nv_bfloat16, y_t)    SYM(__nv_bfloat16, outw_t)
    #undef SYM

    static bool init_done = false;
    static cudaStream_t s2;
    static cudaEvent_t evFork, evA, evB, evR;
    if (!init_done) {
        cudaFuncSetAttribute((const void*)gemm_tc<0>, cudaFuncAttributeMaxDynamicSharedMemorySize, GEMM_SMEM);
        cudaFuncSetAttribute((const void*)gemm_tc<1>, cudaFuncAttributeMaxDynamicSharedMemorySize, GEMM_SMEM);
        cudaFuncSetAttribute((const void*)gemm_tc<2>, cudaFuncAttributeMaxDynamicSharedMemorySize, GEMM_SMEM);
        cudaStreamCreateWithFlags(&s2, cudaStreamNonBlocking);
        cudaEventCreateWithFlags(&evFork, cudaEventDisableTiming);
        cudaEventCreateWithFlags(&evA, cudaEventDisableTiming);
        cudaEventCreateWithFlags(&evB, cudaEventDisableTiming);
        cudaEventCreateWithFlags(&evR, cudaEventDisableTiming);
        init_done = true;
    }

    const int n_x    = LEN * HH / 4;
    const int n_inw  = 2 * DIN * HH / 4;
    const int n_outw = HH * DIN / 4;
    const int n_dtw  = DIN * RR / 4;
    const int n_wpad = XDP * DIN / 4;

    // fork side stream
    cudaEventRecord(evFork, 0);
    cudaStreamWaitEvent(s2, evFork, 0);

    // 0a) critical splits: x, in_w  (main stream)
    {
        SplitArgs a;
        a.s[0] = { x,    (char*)x_t,   HH, LEN,     0 };
        a.s[1] = { in_w, (char*)inw_t, HH, 2 * DIN, n_x };
        a.total = n_x + n_inw;
        a.s[2] = a.s[3] = a.s[4] = a.s[1];
        a.s[2].start = a.s[3].start = a.s[4].start = a.total;
        split_all_kernel<<<(a.total + 255) / 256, 256>>>(a);
        cudaEventRecord(evA, 0);
    }
    // 0b) non-critical splits: wpad, dtw, outw  (side stream)
    {
        SplitArgs a;
        a.s[0] = { xproj_w, (char*)wpad_t, DIN, RR + 2*NS, 0 };
        a.s[1] = { dt_w,    (char*)dtw_t,  RR,  DIN,       n_wpad };
        a.s[2] = { out_w,   (char*)outw_t, DIN, HH,        n_wpad + n_dtw };
        a.total = n_wpad + n_dtw + n_outw;
        a.s[3] = a.s[4] = a.s[2];
        a.s[3].start = a.s[4].start = a.total;
        split_all_kernel<<<(a.total + 255) / 256, 256, 0, s2>>>(a);
        cudaEventRecord(evB, s2);
    }

    // 1a) in_proj xc half: xz[:, 0:2048]  (main stream)
    {
        dim3 grid(DIN / 128, LEN / 128, 1);
        gemm_tc<1><<<grid, 256, GEMM_SMEM>>>(x_t, inw_t, in_b, xz,
                                             HH / 64, HH / 64, HH / 64, 2 * DIN);
    }
    // 1b) in_proj res half: xz[:, 2048:4096]  (side stream, joins before scan_p3)
    {
        cudaStreamWaitEvent(s2, evA, 0);
        const __nv_bfloat16* inw_res =
            (const __nv_bfloat16*)((const char*)inw_t + (size_t)(DIN / 128) * (HH / 64) * PAIR_B);
        dim3 grid(DIN / 128, LEN / 128, 1);
        gemm_tc<1><<<grid, 256, GEMM_SMEM, s2>>>(x_t, inw_res, in_b + DIN, xz + DIN,
                                                 HH / 64, HH / 64, HH / 64, 2 * DIN);
        cudaEventRecord(evR, s2);
    }

    // 2) conv + silu (only reads xc half)
    conv_silu_kernel<<<(LEN * DIN) / 256, 256>>>(conv_w, conv_b, xz, xs, xs_t);
    // 3) x_proj split-K (needs wpad from side stream)
    cudaStreamWaitEvent(0, evB, 0);
    {
        dim3 grid(1, LEN / 128, KSPLIT);
        gemm_tc<0><<<grid, 256, GEMM_SMEM>>>(xs_t, wpad_t, nullptr,
                                             xpart, DIN / 64, DIN / 64,
                                             DIN / 64 / KSPLIT, XDP);
    }
    // 3b) reduce -> xdbl fp32 + interleaved tiled bf16
    reduce_xdbl_kernel<<<(LEN * XDP + 255) / 256, 256>>>(xpart, xdbl, xdbl_t);
    // 4) dt_proj + softplus
    {
        dim3 grid(DIN / 128, LEN / 128, 1);
        gemm_tc<2><<<grid, 256, GEMM_SMEM>>>(xdbl_t, dtw_t, dt_b,
                                             delta, XDP / 64, RR / 64, 1, DIN);
    }
    // 5) chunked scan
    {
        dim3 g1(DIN / SCAN_CH, NCH_L);
        scan_p1_kernel<<<g1, 256>>>(A_log, xdbl, delta, xs, carryA, carryH);
        cudaStreamWaitEvent(0, evR, 0);   // res half of xz needed by p3
        scan_p3_kernel<<<g1, 256>>>(A_log, Dp, xdbl, delta, xs, xz,
                                    carryA, carryH, y_t);
    }
    // 6) out_proj
    {
        dim3 grid(HH / 128, LEN / 128, 1);
        gemm_tc<0><<<grid, 256, GEMM_SMEM>>>(y_t, outw_t, nullptr,
                                             out, DIN / 64, DIN / 64, DIN / 64, HH);
    }
}

// round 17
// speedup vs baseline: 1.1488x; 1.0086x over previous
#include <cuda_runtime.h>
#include <cuda_bf16.h>
#include <math.h>
#include <stdint.h>
#include <string.h>

// Problem constants
static constexpr int LEN = 2048;
static constexpr int HH  = 1024;
static constexpr int DIN = 2048;
static constexpr int NS  = 16;
static constexpr int RR  = 64;
static constexpr int KC  = 4;
static constexpr int XDP = 128;     // padded x_dbl width (96 -> 128)
static constexpr int KSPLIT = 8;    // split-K factor for x_proj
static constexpr int NCH_L = 16;    // scan L-chunks
static constexpr int LCH  = LEN / NCH_L;   // 128

// fp32 scratch
__device__ __align__(16) float g_xz[(size_t)LEN * 2 * DIN];
__device__ __align__(16) float g_xs[(size_t)LEN * DIN];
__device__ __align__(16) float g_xdbl[(size_t)LEN * XDP];
__device__ __align__(16) float g_delta[(size_t)LEN * DIN];
__device__ __align__(16) float g_xpart[(size_t)KSPLIT * LEN * XDP];
__device__ __align__(16) float g_carryA[(size_t)NCH_L * DIN * NS];
__device__ __align__(16) float g_carryH[(size_t)NCH_L * DIN * NS];

// bf16 operand buffers: interleaved hi/lo in SW128-swizzled 32KB-tile-pair
// layout. tensor [rows, K] -> tile pair (rowpanel=row/128, kchunk=col/64);
// byte off = pair*32768 + part*16384 + SW128((row%128)*128 + (col%64)*2)
__device__ __align__(1024) __nv_bfloat16 g_x_t[(size_t)2 * LEN * HH];
__device__ __align__(1024) __nv_bfloat16 g_inw_t[(size_t)2 * 2*DIN * HH];
__device__ __align__(1024) __nv_bfloat16 g_xs_t[(size_t)2 * LEN * DIN];
__device__ __align__(1024) __nv_bfloat16 g_wpad_t[(size_t)2 * XDP * DIN];
__device__ __align__(1024) __nv_bfloat16 g_xdbl_t[(size_t)2 * LEN * XDP];
__device__ __align__(1024) __nv_bfloat16 g_dtw_t[(size_t)2 * DIN * RR];
__device__ __align__(1024) __nv_bfloat16 g_y_t[(size_t)2 * LEN * DIN];
__device__ __align__(1024) __nv_bfloat16 g_outw_t[(size_t)2 * HH * DIN];

#if defined(__CUDA_ARCH_FEAT_SM103_ALL) || defined(__CUDA_ARCH_FEAT_SM100_ALL)
#define HAS_TCGEN05 1
#else
#define HAS_TCGEN05 0
#endif

// ---------------------------------------------------------------------------
// helpers
// ---------------------------------------------------------------------------
__device__ __forceinline__ uint32_t smem_to_u32(const void* smem_ptr) {
    uint32_t addr;
    asm("{ .reg .u64 tmp; cvta.to.shared.u64 tmp, %1; cvt.u32.u64 %0, tmp; }"
        : "=r"(addr) : "l"(smem_ptr));
    return addr;
}

#define SMEM_SWIZZLE_128B(byte_offset) \
    ((byte_offset) ^ (((byte_offset) >> 3) & 0x70))

// interleaved tiled-swizzled byte offset: part 0=hi, 1=lo
__device__ __forceinline__ uint32_t tiled_off2(int row, int col, int K, int part) {
    uint32_t pair = (uint32_t)(row >> 7) * (uint32_t)(K >> 6) + (uint32_t)(col >> 6);
    uint32_t in = (uint32_t)((row & 127) * 128 + (col & 63) * 2);
    return (pair << 15) + ((uint32_t)part << 14) + SMEM_SWIZZLE_128B(in);
}

static constexpr uint64_t SMEM_DESC_BASE_SW128 =
    (uint64_t(2)  << 61) | (uint64_t(1) << 46) | (uint64_t(64) << 32) | (uint64_t(1) << 16);
#define MAKE_SMEM_DESC(base_addr) \
    (SMEM_DESC_BASE_SW128 | ((uint64_t)((base_addr) >> 4) & 0x3FFF))

#if HAS_TCGEN05

#define TCGEN05_ALLOC(smem_result_addr, nCols) \
    asm volatile("tcgen05.alloc.cta_group::1.sync.aligned.shared::cta.b32 [%0], %1;" \
        :: "r"((uint32_t)(smem_result_addr)), "r"((uint32_t)(nCols)) : "memory")
#define TCGEN05_DEALLOC(tmem_addr, nCols) \
    asm volatile("tcgen05.dealloc.cta_group::1.sync.aligned.b32 %0, %1;" \
        :: "r"(tmem_addr), "r"((uint32_t)(nCols)))
#define TCGEN05_RELINQUISH_ALLOC_PERMIT() \
    asm volatile("tcgen05.relinquish_alloc_permit.cta_group::1.sync.aligned;")
#define TCGEN05_COMMIT(mbar_smem_addr) \
    asm volatile("tcgen05.commit.cta_group::1.mbarrier::arrive::one.shared::cluster.b64 [%0];" \
        :: "r"((uint32_t)(mbar_smem_addr)) : "memory")
#define TCGEN05_WAIT_LD() \
    asm volatile("tcgen05.wait::ld.sync.aligned;" ::: "memory")
#define TCGEN05_FENCE_AFTER() \
    asm volatile("tcgen05.fence::after_thread_sync;" ::: "memory")

#define MBARRIER_INIT(mbar_smem_addr, count) \
    asm volatile("mbarrier.init.shared.b64 [%0], %1;" \
        :: "r"((uint32_t)(mbar_smem_addr)), "r"((uint32_t)(count)) : "memory")

#define MBARRIER_EXPECT_TX(mbar_smem_addr, tx_bytes) \
    asm volatile("mbarrier.arrive.expect_tx.shared.b64 _, [%0], %1;" \
        :: "r"((uint32_t)(mbar_smem_addr)), "r"((uint32_t)(tx_bytes)) : "memory")

#define MBARRIER_WAIT_PARITY(mbar_smem_addr, phase_parity) do { \
    uint32_t _mbar = (uint32_t)(mbar_smem_addr); \
    uint32_t _parity = (uint32_t)(phase_parity); \
    uint32_t _done; \
    asm volatile( \
        "{\n\t.reg .pred p;\n\t" \
        "mbarrier.try_wait.parity.acquire.cta.shared::cta.b64 p, [%1], %2;\n\t" \
        "selp.b32 %0, 1, 0, p;\n\t}" \
        : "=r"(_done) : "r"(_mbar), "r"(_parity) : "memory"); \
    if (!_done) { \
        asm volatile( \
            "{\n\t.reg .pred P1;\n\t" \
            "WAIT_LOOP_%=:\n\t" \
            "mbarrier.try_wait.parity.acquire.cta.shared::cta.b64 P1, [%0], %1, 0x989680;\n\t" \
            "@P1 bra.uni WAIT_DONE_%=;\n\t" \
            "bra.uni WAIT_LOOP_%=;\n\t" \
            "WAIT_DONE_%=:\n\t}" \
            :: "r"(_mbar), "r"(_parity) : "memory"); \
    } \
} while(0)

#define TCGEN05_LD_32X32B_X32(r, tmem_addr) \
    asm volatile( \
        "tcgen05.ld.sync.aligned.32x32b.x32.b32 " \
        "{%0, %1, %2, %3, %4, %5, %6, %7, " \
        " %8, %9, %10, %11, %12, %13, %14, %15, " \
        " %16, %17, %18, %19, %20, %21, %22, %23, " \
        " %24, %25, %26, %27, %28, %29, %30, %31}, [%32];" \
        : "=r"((r)[0]),  "=r"((r)[1]),  "=r"((r)[2]),  "=r"((r)[3]), \
          "=r"((r)[4]),  "=r"((r)[5]),  "=r"((r)[6]),  "=r"((r)[7]), \
          "=r"((r)[8]),  "=r"((r)[9]),  "=r"((r)[10]), "=r"((r)[11]), \
          "=r"((r)[12]), "=r"((r)[13]), "=r"((r)[14]), "=r"((r)[15]), \
          "=r"((r)[16]), "=r"((r)[17]), "=r"((r)[18]), "=r"((r)[19]), \
          "=r"((r)[20]), "=r"((r)[21]), "=r"((r)[22]), "=r"((r)[23]), \
          "=r"((r)[24]), "=r"((r)[25]), "=r"((r)[26]), "=r"((r)[27]), \
          "=r"((r)[28]), "=r"((r)[29]), "=r"((r)[30]), "=r"((r)[31]) \
        : "r"(tmem_addr))

__device__ __forceinline__ void mma_f16_ss(uint32_t d_tmem, uint64_t a_desc,
                                           uint64_t b_desc, uint32_t idesc,
                                           bool accum) {
    uint32_t en = accum ? 1u : 0u;
    asm volatile(
        "{\n\t.reg .pred p;\n\t"
        "setp.ne.u32 p, %5, 0;\n\t"
        "tcgen05.mma.cta_group::1.kind::f16 [%0], %1, %2, %3, {%4, %4, %4, %4}, p;\n\t"
        "}"
        :: "r"(d_tmem), "l"(a_desc), "l"(b_desc), "r"(idesc), "r"(0u), "r"(en)
        : "memory");
}

__device__ __forceinline__ void bulk_cp(uint32_t dst, const void* src,
                                        uint32_t bytes, uint32_t mbar) {
    asm volatile(
        "cp.async.bulk.shared::cta.global.mbarrier::complete_tx::bytes [%0], [%1], %2, [%3];"
        :: "r"(dst), "l"(src), "r"(bytes), "r"(mbar) : "memory");
}

#endif // HAS_TCGEN05

// ---------------------------------------------------------------------------
// tcgen05 GEMM: operands in interleaved tiled-swizzled bf16 hi/lo layout;
// each chunk fetched with TWO 32KB cp.async.bulk (A pair, B pair).
// BM=BN=128, BK=64; 3-slot pipeline with lookahead 2: at iteration c, fill
// chunk c+2 gated on MMA(c-1) (already complete -> fast path), so MMA(c+1)
// is issued while MMA(c) still executes and the tensor pipe never drains.
// 3-term split (ah*bh + ah*bl + al*bh).
// EPI: 0=none, 1=+bias, 2=softplus(acc+bias).  Split-K via blockIdx.z.
// ---------------------------------------------------------------------------
static constexpr int TILE_B = 16384;
static constexpr int PAIR_B = 32768;
static constexpr int STAGE_B = 4 * TILE_B;              // 64 KB
static constexpr int BUF0 = 1024;
static constexpr int GEMM_SMEM = BUF0 + 3 * STAGE_B;    // 197632 B

template <int EPI>
__global__ __launch_bounds__(256) void gemm_tc(
    const __nv_bfloat16* __restrict__ a_t, const __nv_bfloat16* __restrict__ b_t,
    const float* __restrict__ bias, float* __restrict__ C,
    int nkA, int nkB, int nch, int ldc)
{
#if HAS_TCGEN05
    extern __shared__ char smem[];
    uint32_t sb = smem_to_u32(smem);
    const int tid = threadIdx.x;
    const int wid = tid >> 5, lane = tid & 31;
    const int bm = blockIdx.y * 128, bn = blockIdx.x * 128;
    const int kc0 = blockIdx.z * nch;
    C += (size_t)blockIdx.z * (size_t)(gridDim.y * 128) * ldc;

    if (wid == 0) TCGEN05_ALLOC(sb, 128);
    if (tid == 0) {
        MBARRIER_INIT(sb + 8, 1);  MBARRIER_INIT(sb + 16, 1); MBARRIER_INIT(sb + 24, 1);
        MBARRIER_INIT(sb + 32, 1); MBARRIER_INIT(sb + 40, 1); MBARRIER_INIT(sb + 48, 1);
    }
    __syncthreads();
    uint32_t tmem;
    asm volatile("ld.shared.b32 %0, [%1];" : "=r"(tmem) : "r"(sb));

    const uint32_t idesc = (1u << 4) | (1u << 7) | (1u << 10) |
                           (16u << 17) | (8u << 24);

    if (tid == 0) {
        const char* pa = (const char*)a_t;
        const char* pb = (const char*)b_t;
        const size_t abase = (size_t)blockIdx.y * nkA + kc0;
        const size_t bbase = (size_t)blockIdx.x * nkB + kc0;

        auto fill = [&](int f) {
            int slot = f % 3;
            uint32_t st = sb + BUF0 + (uint32_t)slot * STAGE_B;
            uint32_t mb = sb + 8 + 8 * slot;
            MBARRIER_EXPECT_TX(mb, STAGE_B);
            bulk_cp(st,          pa + (abase + f) * PAIR_B, PAIR_B, mb);
            bulk_cp(st + PAIR_B, pb + (bbase + f) * PAIR_B, PAIR_B, mb);
        };

        // prologue: lookahead 2
        int npro = nch < 2 ? nch : 2;
        for (int s = 0; s < npro; s++) fill(s);

        for (int c = 0; c < nch; c++) {
            const int slot = c % 3;
            const int ph = (c / 3) & 1;
            const uint32_t st = sb + BUF0 + (uint32_t)slot * STAGE_B;
            MBARRIER_WAIT_PARITY(sb + 8 + 8 * slot, ph);   // fill(c) landed
            uint64_t ah = MAKE_SMEM_DESC(st);
            uint64_t al = MAKE_SMEM_DESC(st + TILE_B);
            uint64_t bh = MAKE_SMEM_DESC(st + 2 * TILE_B);
            uint64_t bl = MAKE_SMEM_DESC(st + 3 * TILE_B);
            const bool accc = (c > 0);
#pragma unroll
            for (int k = 0; k < 4; k++) {
                mma_f16_ss(tmem, ah + k * 2, bh + k * 2, idesc, accc || k > 0);
                mma_f16_ss(tmem, ah + k * 2, bl + k * 2, idesc, true);
                mma_f16_ss(tmem, al + k * 2, bh + k * 2, idesc, true);
            }
            TCGEN05_COMMIT(sb + 32 + 8 * slot);
            if (c + 2 < nch) {
                int m = c - 1;   // fill(c+2) reuses slot(c-1): gate on MMA(c-1)
                if (m >= 0)
                    MBARRIER_WAIT_PARITY(sb + 32 + 8 * (m % 3), (m / 3) & 1);
                fill(c + 2);
            }
        }
        MBARRIER_WAIT_PARITY(sb + 32 + 8 * ((nch - 1) % 3), ((nch - 1) / 3) & 1);
    }

    __syncthreads();
    TCGEN05_FENCE_AFTER();

    if (wid < 4) {
        const int row = bm + wid * 32 + lane;
#pragma unroll
        for (int c32 = 0; c32 < 4; c32++) {
            uint32_t r[32];
            TCGEN05_LD_32X32B_X32(r, tmem + c32 * 32);
            TCGEN05_WAIT_LD();
            float* crow = &C[(size_t)row * ldc + bn + c32 * 32];
#pragma unroll
            for (int j = 0; j < 8; j++) {
                float4 v;
                v.x = __uint_as_float(r[4 * j + 0]);
                v.y = __uint_as_float(r[4 * j + 1]);
                v.z = __uint_as_float(r[4 * j + 2]);
                v.w = __uint_as_float(r[4 * j + 3]);
                if (EPI >= 1) {
                    float4 bv = *reinterpret_cast<const float4*>(
                        &bias[bn + c32 * 32 + 4 * j]);
                    v.x += bv.x; v.y += bv.y; v.z += bv.z; v.w += bv.w;
                }
                if (EPI == 2) {
                    v.x = (v.x > 20.f) ? v.x : log1pf(__expf(v.x));
                    v.y = (v.y > 20.f) ? v.y : log1pf(__expf(v.y));
                    v.z = (v.z > 20.f) ? v.z : log1pf(__expf(v.z));
                    v.w = (v.w > 20.f) ? v.w : log1pf(__expf(v.w));
                }
                *reinterpret_cast<float4*>(&crow[4 * j]) = v;
            }
        }
    }
    __syncthreads();
    if (wid == 0) {
        TCGEN05_RELINQUISH_ALLOC_PERMIT();
        TCGEN05_DEALLOC(tmem, 128);
    }
#endif // HAS_TCGEN05
}

// ---------------------------------------------------------------------------
// Fused fp32 -> interleaved tiled-swizzled bf16 hi/lo split (up to 5 tensors).
// ---------------------------------------------------------------------------
struct SplitSeg {
    const float* src; char* dst;
    int K; int rows_valid; int start;
};
struct SplitArgs { SplitSeg s[5]; int total; };

__global__ __launch_bounds__(256) void split_all_kernel(SplitArgs a)
{
    int i = blockIdx.x * 256 + threadIdx.x;
    if (i >= a.total) return;
    int si = 0;
#pragma unroll
    for (int t = 1; t < 5; t++)
        if (i >= a.s[t].start) si = t;
    const SplitSeg g = a.s[si];
    int li = i - g.start;
    int kq = g.K >> 2;
    int row = li / kq, col = (li - row * kq) * 4;
    float4 v = make_float4(0.f, 0.f, 0.f, 0.f);
    if (row < g.rows_valid)
        v = *reinterpret_cast<const float4*>(&g.src[(size_t)row * g.K + col]);
    __nv_bfloat16 h0 = __float2bfloat16(v.x), h1 = __float2bfloat16(v.y);
    __nv_bfloat16 h2 = __float2bfloat16(v.z), h3 = __float2bfloat16(v.w);
    __nv_bfloat16 l0 = __float2bfloat16(v.x - __bfloat162float(h0));
    __nv_bfloat16 l1 = __float2bfloat16(v.y - __bfloat162float(h1));
    __nv_bfloat16 l2 = __float2bfloat16(v.z - __bfloat162float(h2));
    __nv_bfloat16 l3 = __float2bfloat16(v.w - __bfloat162float(h3));
    uint32_t offh = tiled_off2(row, col, g.K, 0);
    uint32_t offl = tiled_off2(row, col, g.K, 1);
    __nv_bfloat162 hA(h0, h1), hB(h2, h3), lA(l0, l1), lB(l2, l3);
    uint2 hu, lu;
    memcpy(&hu.x, &hA, 4); memcpy(&hu.y, &hB, 4);
    memcpy(&lu.x, &lA, 4); memcpy(&lu.y, &lB, 4);
    *reinterpret_cast<uint2*>(g.dst + offh) = hu;
    *reinterpret_cast<uint2*>(g.dst + offl) = lu;
}

__device__ __forceinline__ void split_store_tiled2(float v, __nv_bfloat16* dst,
                                                   int row, int col, int K) {
    __nv_bfloat16 h = __float2bfloat16(v);
    *reinterpret_cast<__nv_bfloat16*>((char*)dst + tiled_off2(row, col, K, 0)) = h;
    *reinterpret_cast<__nv_bfloat16*>((char*)dst + tiled_off2(row, col, K, 1)) =
        __float2bfloat16(v - __bfloat162float(h));
}

// ---------------------------------------------------------------------------
// conv1d (K=4, causal) + SiLU; writes xs fp32 + interleaved tiled bf16
// ---------------------------------------------------------------------------
__global__ __launch_bounds__(256) void conv_silu_kernel(
    const float* __restrict__ conv_w, const float* __restrict__ conv_b,
    const float* __restrict__ xz, float* __restrict__ xs,
    __nv_bfloat16* __restrict__ xs_t)
{
    int idx = blockIdx.x * blockDim.x + threadIdx.x;
    if (idx >= LEN * DIN) return;
    int l = idx / DIN, d = idx % DIN;
    float acc = conv_b[d];
#pragma unroll
    for (int k = 0; k < KC; k++) {
        int ls = l - (KC - 1) + k;
        if (ls >= 0)
            acc += conv_w[d * KC + k] * xz[(size_t)ls * (2 * DIN) + d];
    }
    float v = acc / (1.f + __expf(-acc));
    xs[idx] = v;
    split_store_tiled2(v, xs_t, l, d, DIN);
}

// ---------------------------------------------------------------------------
// reduce split-K partials -> xdbl fp32 + interleaved tiled bf16
// ---------------------------------------------------------------------------
__global__ __launch_bounds__(256) void reduce_xdbl_kernel(
    const float* __restrict__ part, float* __restrict__ xdbl,
    __nv_bfloat16* __restrict__ xdbl_t)
{
    int i = blockIdx.x * 256 + threadIdx.x;
    if (i >= LEN * XDP) return;
    float s = 0.f;
#pragma unroll
    for (int z = 0; z < KSPLIT; z++)
        s += part[(size_t)z * LEN * XDP + i];
    xdbl[i] = s;
    split_store_tiled2(s, xdbl_t, i / XDP, i % XDP, XDP);
}

// ---------------------------------------------------------------------------
// Chunked selective scan (two-phase).
// ---------------------------------------------------------------------------
static constexpr int SCAN_TL = 64;
static constexpr int SCAN_CH = 16;

__global__ __launch_bounds__(256) void scan_p1_kernel(
    const float* __restrict__ A_log,
    const float* __restrict__ xdbl, const float* __restrict__ delta_g,
    const float* __restrict__ xs_g,
    float* __restrict__ carryA, float* __restrict__ carryH)
{
    __shared__ float sB[SCAN_TL][NS];
    __shared__ float sDelta[SCAN_TL][SCAN_CH];
    __shared__ float sXs[SCAN_TL][SCAN_CH];

    const int d0 = blockIdx.x * SCAN_CH;
    const int jch = blockIdx.y;
    const int lbase = jch * LCH;
    const int tid = threadIdx.x;
    const int warp = tid >> 5, lane = tid & 31;
    const int sub = lane >> 4, n = lane & 15;
    const int ch = warp * 2 + sub;
    const int d = d0 + ch;

    const float a = -__expf(A_log[d * NS + n]);
    float h = 0.f, ap = 1.f;

    for (int l0 = lbase; l0 < lbase + LCH; l0 += SCAN_TL) {
        for (int i = tid; i < SCAN_TL * NS; i += 256) {
            int row = i >> 4, c = i & 15;
            sB[row][c] = xdbl[(size_t)(l0 + row) * XDP + RR + c];
        }
        for (int i = tid; i < SCAN_TL * SCAN_CH; i += 256) {
            int row = i >> 4, c = i & 15;
            sDelta[row][c] = delta_g[(size_t)(l0 + row) * DIN + d0 + c];
            sXs[row][c]    = xs_g[(size_t)(l0 + row) * DIN + d0 + c];
        }
        __syncthreads();
#pragma unroll 4
        for (int l = 0; l < SCAN_TL; l++) {
            float dv = sDelta[l][ch];
            float dA = __expf(dv * a);
            h = dA * h + (dv * sXs[l][ch]) * sB[l][n];
            ap *= dA;
        }
        __syncthreads();
    }
    size_t o = (size_t)jch * DIN * NS + (size_t)d * NS + n;
    carryA[o] = ap;
    carryH[o] = h;
}

__global__ __launch_bounds__(256) void scan_p3_kernel(
    const float* __restrict__ A_log, const float* __restrict__ Dp,
    const float* __restrict__ xdbl, const float* __restrict__ delta_g,
    const float* __restrict__ xs_g, const float* __restrict__ xz,
    const float* __restrict__ carryA, const float* __restrict__ carryH,
    __nv_bfloat16* __restrict__ y_t)
{
    __shared__ float sBC[SCAN_TL][32];
    __shared__ float sDelta[SCAN_TL][SCAN_CH];
    __shared__ float sXs[SCAN_TL][SCAN_CH];
    __shared__ float sRes[SCAN_TL][SCAN_CH];
    __shared__ float sY[SCAN_TL][SCAN_CH];

    const int d0 = blockIdx.x * SCAN_CH;
    const int jch = blockIdx.y;
    const int lbase = jch * LCH;
    const int tid = threadIdx.x;
    const int warp = tid >> 5, lane = tid & 31;
    const int sub = lane >> 4, n = lane & 15;
    const int ch = warp * 2 + sub;
    const int d = d0 + ch;

    const float a = -__expf(A_log[d * NS + n]);
    const float Dv = Dp[d];

    float h = 0.f;
    for (int j = 0; j < jch; j++) {
        size_t o = (size_t)j * DIN * NS + (size_t)d * NS + n;
        h = carryA[o] * h + carryH[o];
    }

    for (int l0 = lbase; l0 < lbase + LCH; l0 += SCAN_TL) {
        for (int i = tid; i < SCAN_TL * 32; i += 256) {
            int row = i >> 5, c = i & 31;
            sBC[row][c] = xdbl[(size_t)(l0 + row) * XDP + RR + c];
        }
        for (int i = tid; i < SCAN_TL * SCAN_CH; i += 256) {
            int row = i >> 4, c = i & 15;
            sDelta[row][c] = delta_g[(size_t)(l0 + row) * DIN + d0 + c];
            sXs[row][c]    = xs_g[(size_t)(l0 + row) * DIN + d0 + c];
            float r = xz[(size_t)(l0 + row) * (2 * DIN) + DIN + d0 + c];
            sRes[row][c]   = r / (1.f + __expf(-r));
        }
        __syncthreads();

#pragma unroll 4
        for (int l = 0; l < SCAN_TL; l++) {
            float dv = sDelta[l][ch];
            float xv = sXs[l][ch];
            float dA = __expf(dv * a);
            h = dA * h + (dv * xv) * sBC[l][n];
            float p = sBC[l][16 + n] * h;
            p += __shfl_xor_sync(0xffffffffu, p, 8);
            p += __shfl_xor_sync(0xffffffffu, p, 4);
            p += __shfl_xor_sync(0xffffffffu, p, 2);
            p += __shfl_xor_sync(0xffffffffu, p, 1);
            if (n == 0)
                sY[l][ch] = (p + xv * Dv) * sRes[l][ch];
        }
        __syncthreads();

        for (int i = tid; i < SCAN_TL * SCAN_CH; i += 256) {
            int row = i >> 4, c = i & 15;
            split_store_tiled2(sY[row][c], y_t, l0 + row, d0 + c, DIN);
        }
        __syncthreads();
    }
}

// ---------------------------------------------------------------------------

extern "C" void kernel_launch(void* const* d_in, const int* in_sizes, int n_in,
                              void* d_out, int out_size)
{
    const float* x       = (const float*)d_in[0];
    const float* in_w    = (const float*)d_in[1];
    const float* in_b    = (const float*)d_in[2];
    const float* conv_w  = (const float*)d_in[3];
    const float* conv_b  = (const float*)d_in[4];
    const float* xproj_w = (const float*)d_in[5];
    const float* dt_w    = (const float*)d_in[6];
    const float* dt_b    = (const float*)d_in[7];
    const float* A_log   = (const float*)d_in[8];
    const float* Dp      = (const float*)d_in[9];
    const float* out_w   = (const float*)d_in[10];
    float* out = (float*)d_out;

    #define SYM(T, name) T* name; { void* p_; cudaGetSymbolAddress(&p_, g_##name); name = (T*)p_; }
    SYM(float, xz) SYM(float, xs) SYM(float, xdbl) SYM(float, delta) SYM(float, xpart)
    SYM(float, carryA) SYM(float, carryH)
    SYM(__nv_bfloat16, x_t)    SYM(__nv_bfloat16, inw_t)
    SYM(__nv_bfloat16, xs_t)   SYM(__nv_bfloat16, wpad_t)
    SYM(__nv_bfloat16, xdbl_t) SYM(__nv_bfloat16, dtw_t)
    SYM(__nv_bfloat16, y_t)    SYM(__nv_bfloat16, outw_t)
    #undef SYM

    static bool init_done = false;
    static cudaStream_t s2;
    static cudaEvent_t evFork, evA, evB, evR;
    if (!init_done) {
        cudaFuncSetAttribute((const void*)gemm_tc<0>, cudaFuncAttributeMaxDynamicSharedMemorySize, GEMM_SMEM);
        cudaFuncSetAttribute((const void*)gemm_tc<1>, cudaFuncAttributeMaxDynamicSharedMemorySize, GEMM_SMEM);
        cudaFuncSetAttribute((const void*)gemm_tc<2>, cudaFuncAttributeMaxDynamicSharedMemorySize, GEMM_SMEM);
        cudaStreamCreateWithFlags(&s2, cudaStreamNonBlocking);
        cudaEventCreateWithFlags(&evFork, cudaEventDisableTiming);
        cudaEventCreateWithFlags(&evA, cudaEventDisableTiming);
        cudaEventCreateWithFlags(&evB, cudaEventDisableTiming);
        cudaEventCreateWithFlags(&evR, cudaEventDisableTiming);
        init_done = true;
    }

    const int n_x    = LEN * HH / 4;
    const int n_inw  = 2 * DIN * HH / 4;
    const int n_outw = HH * DIN / 4;
    const int n_dtw  = DIN * RR / 4;
    const int n_wpad = XDP * DIN / 4;

    // fork side stream
    cudaEventRecord(evFork, 0);
    cudaStreamWaitEvent(s2, evFork, 0);

    // 0a) critical splits: x, in_w  (main stream)
    {
        SplitArgs a;
        a.s[0] = { x,    (char*)x_t,   HH, LEN,     0 };
        a.s[1] = { in_w, (char*)inw_t, HH, 2 * DIN, n_x };
        a.total = n_x + n_inw;
        a.s[2] = a.s[3] = a.s[4] = a.s[1];
        a.s[2].start = a.s[3].start = a.s[4].start = a.total;
        split_all_kernel<<<(a.total + 255) / 256, 256>>>(a);
        cudaEventRecord(evA, 0);
    }
    // 0b) non-critical splits: wpad, dtw, outw  (side stream)
    {
        SplitArgs a;
        a.s[0] = { xproj_w, (char*)wpad_t, DIN, RR + 2*NS, 0 };
        a.s[1] = { dt_w,    (char*)dtw_t,  RR,  DIN,       n_wpad };
        a.s[2] = { out_w,   (char*)outw_t, DIN, HH,        n_wpad + n_dtw };
        a.total = n_wpad + n_dtw + n_outw;
        a.s[3] = a.s[4] = a.s[2];
        a.s[3].start = a.s[4].start = a.total;
        split_all_kernel<<<(a.total + 255) / 256, 256, 0, s2>>>(a);
        cudaEventRecord(evB, s2);
    }

    // 1a) in_proj xc half: xz[:, 0:2048]  (main stream)
    {
        dim3 grid(DIN / 128, LEN / 128, 1);
        gemm_tc<1><<<grid, 256, GEMM_SMEM>>>(x_t, inw_t, in_b, xz,
                                             HH / 64, HH / 64, HH / 64, 2 * DIN);
    }
    // 1b) in_proj res half: xz[:, 2048:4096]  (side stream, joins before scan_p3)
    {
        cudaStreamWaitEvent(s2, evA, 0);
        const __nv_bfloat16* inw_res =
            (const __nv_bfloat16*)((const char*)inw_t + (size_t)(DIN / 128) * (HH / 64) * PAIR_B);
        dim3 grid(DIN / 128, LEN / 128, 1);
        gemm_tc<1><<<grid, 256, GEMM_SMEM, s2>>>(x_t, inw_res, in_b + DIN, xz + DIN,
                                                 HH / 64, HH / 64, HH / 64, 2 * DIN);
        cudaEventRecord(evR, s2);
    }

    // 2) conv + silu (only reads xc half)
    conv_silu_kernel<<<(LEN * DIN) / 256, 256>>>(conv_w, conv_b, xz, xs, xs_t);
    // 3) x_proj split-K (needs wpad from side stream)
    cudaStreamWaitEvent(0, evB, 0);
    {
        dim3 grid(1, LEN / 128, KSPLIT);
        gemm_tc<0><<<grid, 256, GEMM_SMEM>>>(xs_t, wpad_t, nullptr,
                                             xpart, DIN / 64, DIN / 64,
                                             DIN / 64 / KSPLIT, XDP);
    }
    // 3b) reduce -> xdbl fp32 + interleaved tiled bf16
    reduce_xdbl_kernel<<<(LEN * XDP + 255) / 256, 256>>>(xpart, xdbl, xdbl_t);
    // 4) dt_proj + softplus
    {
        dim3 grid(DIN / 128, LEN / 128, 1);
        gemm_tc<2><<<grid, 256, GEMM_SMEM>>>(xdbl_t, dtw_t, dt_b,
                                             delta, XDP / 64, RR / 64, 1, DIN);
    }
    // 5) chunked scan
    {
        dim3 g1(DIN / SCAN_CH, NCH_L);
        scan_p1_kernel<<<g1, 256>>>(A_log, xdbl, delta, xs, carryA, carryH);
        cudaStreamWaitEvent(0, evR, 0);   // res half of xz needed by p3
        scan_p3_kernel<<<g1, 256>>>(A_log, Dp, xdbl, delta, xs, xz,
                                    carryA, carryH, y_t);
    }
    // 6) out_proj
    {
        dim3 grid(HH / 128, LEN / 128, 1);
        gemm_tc<0><<<grid, 256, GEMM_SMEM>>>(y_t, outw_t, nullptr,
                                             out, DIN / 64, DIN / 64, DIN / 64, HH);
    }
}